// round 5
// baseline (speedup 1.0000x reference)
#include <cuda_runtime.h>
#include <cuda_bf16.h>
#include <cstdint>

#define N_NODES 50000
#define N_EDGES_MAX 600000
#define FDIM    128
#define EPS     1e-5f
#define NB      ((N_NODES + 255) / 256)   // 196 blocks for per-chunk scan

// ---------------------------------------------------------------------------
// Scratch (static device globals — no allocation allowed)
// ---------------------------------------------------------------------------
__device__ __align__(16) float g_bufA[(size_t)N_NODES * FDIM];
__device__ __align__(16) float g_bufB[(size_t)N_NODES * FDIM];
__device__ __align__(16) int   g_cnt   [N_NODES];
__device__ __align__(16) int   g_off   [N_NODES];
__device__ __align__(16) int   g_cursor[N_NODES];
__device__ __align__(16) int   g_part  [256];
__device__ __align__(16) float g_dinv  [N_NODES];
__device__ __align__(16) float g_h3    [N_NODES];
__device__ __align__(16) int   g_srcs  [N_EDGES_MAX];
__device__ __align__(16) float g_nrm   [N_EDGES_MAX];

// ---------------------------------------------------------------------------
// Zero int buffer
// ---------------------------------------------------------------------------
__global__ void zero_int_kernel(int* __restrict__ p, int n) {
    int i = blockIdx.x * blockDim.x + threadIdx.x;
    if (i < n) p[i] = 0;
}

// Degree count: cnt[dst]++ for every edge  (edge_index marshaled as int32)
__global__ void count_deg_kernel(const int* __restrict__ ei, int nE,
                                 int* __restrict__ cnt) {
    int e = blockIdx.x * blockDim.x + threadIdx.x;
    if (e >= nE) return;
    atomicAdd(&cnt[ei[nE + e]], 1);
}

// dinv[i] = rsqrt(cnt[i] + 1)
__global__ void dinv_kernel(const int* __restrict__ cnt, float* __restrict__ dinv, int n) {
    int i = blockIdx.x * blockDim.x + threadIdx.x;
    if (i < n) dinv[i] = rsqrtf((float)cnt[i] + 1.0f);
}

// ---------------------------------------------------------------------------
// Exclusive scan of cnt -> off  (3-phase: per-block sums, scan sums, rescan)
// ---------------------------------------------------------------------------
__global__ void partial_sum_kernel(const int* __restrict__ cnt, int* __restrict__ part, int n) {
    __shared__ int s[256];
    int t = threadIdx.x;
    int i = blockIdx.x * 256 + t;
    s[t] = (i < n) ? cnt[i] : 0;
    __syncthreads();
    for (int d = 128; d > 0; d >>= 1) {
        if (t < d) s[t] += s[t + d];
        __syncthreads();
    }
    if (t == 0) part[blockIdx.x] = s[0];
}

__global__ void scan_partials_kernel(int* __restrict__ part, int nb) {
    __shared__ int s[256];
    int t = threadIdx.x;
    int v = (t < nb) ? part[t] : 0;
    s[t] = v;
    __syncthreads();
    // Hillis-Steele inclusive scan
    for (int d = 1; d < 256; d <<= 1) {
        int u = (t >= d) ? s[t - d] : 0;
        __syncthreads();
        s[t] += u;
        __syncthreads();
    }
    if (t < nb) part[t] = s[t] - v;   // exclusive
}

__global__ void chunk_scan_kernel(const int* __restrict__ cnt, const int* __restrict__ part,
                                  int* __restrict__ off, int* __restrict__ cursor, int n) {
    __shared__ int s[256];
    int t = threadIdx.x;
    int i = blockIdx.x * 256 + t;
    int c = (i < n) ? cnt[i] : 0;
    s[t] = c;
    __syncthreads();
    for (int d = 1; d < 256; d <<= 1) {
        int u = (t >= d) ? s[t - d] : 0;
        __syncthreads();
        s[t] += u;
        __syncthreads();
    }
    if (i < n) {
        int o = part[blockIdx.x] + s[t] - c;   // exclusive position
        off[i] = o;
        cursor[i] = o;
    }
}

// Fill CSR: srcs[pos] = src, nrm[pos] = dinv[src]*dinv[dst]
__global__ void fill_kernel(const int* __restrict__ ei, int nE,
                            int* __restrict__ cursor, const float* __restrict__ dinv,
                            int* __restrict__ srcs, float* __restrict__ nrm) {
    int e = blockIdx.x * blockDim.x + threadIdx.x;
    if (e >= nE) return;
    int src = ei[e];
    int dst = ei[nE + e];
    int pos = atomicAdd(&cursor[dst], 1);
    srcs[pos] = src;
    nrm[pos]  = dinv[src] * dinv[dst];
}

// ---------------------------------------------------------------------------
// Tiled fp32 GEMM: C[M,128] = A[M,128] @ W[128,128]
// ---------------------------------------------------------------------------
__global__ __launch_bounds__(256, 3)
void gemm128_kernel(const float* __restrict__ A, const float* __restrict__ W,
                    float* __restrict__ C, int M) {
    __shared__ float As[16][65];
    __shared__ float Bs[16][128];

    const int tid = threadIdx.x;
    const int tr  = tid >> 5;
    const int tc  = tid & 31;
    const int row0 = blockIdx.x * 64;
    const int arow = tid >> 2;
    const int ak4  = (tid & 3) * 4;

    float acc[8][4];
    #pragma unroll
    for (int r = 0; r < 8; r++)
        #pragma unroll
        for (int c = 0; c < 4; c++) acc[r][c] = 0.f;

    for (int k0 = 0; k0 < 128; k0 += 16) {
        float4 av = make_float4(0.f, 0.f, 0.f, 0.f);
        int gr = row0 + arow;
        if (gr < M) av = *(const float4*)(A + (size_t)gr * FDIM + k0 + ak4);
        As[ak4 + 0][arow] = av.x;
        As[ak4 + 1][arow] = av.y;
        As[ak4 + 2][arow] = av.z;
        As[ak4 + 3][arow] = av.w;

        #pragma unroll
        for (int i = 0; i < 2; i++) {
            int f   = tid + i * 256;
            int bkk = f >> 5;
            int bn4 = (f & 31) * 4;
            *(float4*)&Bs[bkk][bn4] =
                *(const float4*)(W + (size_t)(k0 + bkk) * FDIM + bn4);
        }
        __syncthreads();

        #pragma unroll
        for (int kk = 0; kk < 16; kk++) {
            float4 bv = *(const float4*)&Bs[kk][tc * 4];
            #pragma unroll
            for (int r = 0; r < 8; r++) {
                float a = As[kk][tr * 8 + r];
                acc[r][0] += a * bv.x;
                acc[r][1] += a * bv.y;
                acc[r][2] += a * bv.z;
                acc[r][3] += a * bv.w;
            }
        }
        __syncthreads();
    }

    #pragma unroll
    for (int r = 0; r < 8; r++) {
        int gr = row0 + tr * 8 + r;
        if (gr < M)
            *(float4*)(C + (size_t)gr * FDIM + tc * 4) =
                make_float4(acc[r][0], acc[r][1], acc[r][2], acc[r][3]);
    }
}

// ---------------------------------------------------------------------------
// Fused CSR gather + self-loop + bias + LayerNorm + ReLU. Warp per node.
// out must NOT alias h.
// ---------------------------------------------------------------------------
__global__ __launch_bounds__(256)
void aggregate_ln_relu_kernel(const float* __restrict__ h,
                              const int* __restrict__ off, const int* __restrict__ cnt,
                              const int* __restrict__ srcs, const float* __restrict__ nrm,
                              const float* __restrict__ dinv, const float* __restrict__ bias,
                              const float* __restrict__ gamma, const float* __restrict__ beta,
                              float* __restrict__ out, int n) {
    int node = (blockIdx.x * blockDim.x + threadIdx.x) >> 5;
    int lane = threadIdx.x & 31;
    if (node >= n) return;

    float di = dinv[node];
    float d2 = di * di;

    // self-loop term
    float4 acc = *((const float4*)(h + (size_t)node * FDIM) + lane);
    acc.x *= d2; acc.y *= d2; acc.z *= d2; acc.w *= d2;

    int start = off[node];
    int m     = cnt[node];
    for (int base = 0; base < m; base += 32) {
        int k = min(32, m - base);
        int   s  = 0;
        float nm = 0.f;
        if (lane < k) {
            s  = srcs[start + base + lane];
            nm = nrm [start + base + lane];
        }
        for (int j = 0; j < k; j++) {
            int   sj = __shfl_sync(0xFFFFFFFFu, s,  j);
            float nj = __shfl_sync(0xFFFFFFFFu, nm, j);
            float4 v = *((const float4*)(h + (size_t)sj * FDIM) + lane);
            acc.x += v.x * nj; acc.y += v.y * nj;
            acc.z += v.z * nj; acc.w += v.w * nj;
        }
    }

    float4 bv = *((const float4*)bias + lane);
    acc.x += bv.x; acc.y += bv.y; acc.z += bv.z; acc.w += bv.w;

    // LayerNorm over 128 features (warp reduce)
    float sum = acc.x + acc.y + acc.z + acc.w;
    #pragma unroll
    for (int o = 16; o; o >>= 1) sum += __shfl_xor_sync(0xFFFFFFFFu, sum, o);
    float mu = sum * (1.0f / FDIM);

    float tx = acc.x - mu, ty = acc.y - mu, tz = acc.z - mu, tw = acc.w - mu;
    float q = tx * tx + ty * ty + tz * tz + tw * tw;
    #pragma unroll
    for (int o = 16; o; o >>= 1) q += __shfl_xor_sync(0xFFFFFFFFu, q, o);
    float rstd = rsqrtf(q * (1.0f / FDIM) + EPS);

    float4 gv = *((const float4*)gamma + lane);
    float4 be = *((const float4*)beta  + lane);

    float4 o4;
    o4.x = fmaxf(tx * rstd * gv.x + be.x, 0.f);
    o4.y = fmaxf(ty * rstd * gv.y + be.y, 0.f);
    o4.z = fmaxf(tz * rstd * gv.z + be.z, 0.f);
    o4.w = fmaxf(tw * rstd * gv.w + be.w, 0.f);

    *((float4*)(out + (size_t)node * FDIM) + lane) = o4;
}

// ---------------------------------------------------------------------------
// Layer 3: h3 = X @ W3 (128 -> 1). Warp per node.
// ---------------------------------------------------------------------------
__global__ __launch_bounds__(256)
void gemv3_kernel(const float* __restrict__ X, const float* __restrict__ W3,
                  float* __restrict__ h3, int n) {
    int node = (blockIdx.x * blockDim.x + threadIdx.x) >> 5;
    int lane = threadIdx.x & 31;
    if (node >= n) return;
    float4 a = *((const float4*)(X + (size_t)node * FDIM) + lane);
    float4 w = *((const float4*)W3 + lane);
    float s = a.x * w.x + a.y * w.y + a.z * w.z + a.w * w.w;
    #pragma unroll
    for (int o = 16; o; o >>= 1) s += __shfl_xor_sync(0xFFFFFFFFu, s, o);
    if (lane == 0) h3[node] = s;
}

// Layer-3 gather (thread per node): out[i] = sum_e h3[src]*nrm + h3[i]*dinv^2 + b3
__global__ void gather3_kernel(const float* __restrict__ h3,
                               const int* __restrict__ off, const int* __restrict__ cnt,
                               const int* __restrict__ srcs, const float* __restrict__ nrm,
                               const float* __restrict__ dinv, const float* __restrict__ b3,
                               float* __restrict__ out, int n) {
    int i = blockIdx.x * blockDim.x + threadIdx.x;
    if (i >= n) return;
    float di = dinv[i];
    float acc = h3[i] * di * di;
    int start = off[i], m = cnt[i];
    for (int e = 0; e < m; e++)
        acc += h3[srcs[start + e]] * nrm[start + e];
    out[i] = acc + b3[0];
}

// ---------------------------------------------------------------------------
// Launch
// ---------------------------------------------------------------------------
extern "C" void kernel_launch(void* const* d_in, const int* in_sizes, int n_in,
                              void* d_out, int out_size) {
    const float* x     = (const float*)d_in[0];
    const int*   ei    = (const int*)d_in[1];     // int64 marshaled to int32
    const float* W1    = (const float*)d_in[2];
    const float* b1    = (const float*)d_in[3];
    const float* W2    = (const float*)d_in[4];
    const float* b2    = (const float*)d_in[5];
    const float* W3    = (const float*)d_in[6];
    const float* b3    = (const float*)d_in[7];
    const float* gamma = (const float*)d_in[8];
    const float* beta  = (const float*)d_in[9];
    float*       out   = (float*)d_out;

    const int nE = in_sizes[1] / 2;
    const int n  = N_NODES;

    float *bufA, *bufB, *dinv, *h3, *nrm;
    int   *cnt, *off, *cursor, *part, *srcs;
    cudaGetSymbolAddress((void**)&bufA,   g_bufA);
    cudaGetSymbolAddress((void**)&bufB,   g_bufB);
    cudaGetSymbolAddress((void**)&cnt,    g_cnt);
    cudaGetSymbolAddress((void**)&off,    g_off);
    cudaGetSymbolAddress((void**)&cursor, g_cursor);
    cudaGetSymbolAddress((void**)&part,   g_part);
    cudaGetSymbolAddress((void**)&dinv,   g_dinv);
    cudaGetSymbolAddress((void**)&h3,     g_h3);
    cudaGetSymbolAddress((void**)&srcs,   g_srcs);
    cudaGetSymbolAddress((void**)&nrm,    g_nrm);

    const int egrid = (nE + 255) / 256;
    const int ngrid = (n + 255) / 256;
    const int warp_grid = (n * 32 + 255) / 256;
    const int gemm_grid = (n + 63) / 64;

    // --- CSR build ---
    zero_int_kernel<<<ngrid, 256>>>(cnt, n);
    count_deg_kernel<<<egrid, 256>>>(ei, nE, cnt);
    dinv_kernel<<<ngrid, 256>>>(cnt, dinv, n);
    partial_sum_kernel<<<NB, 256>>>(cnt, part, n);
    scan_partials_kernel<<<1, 256>>>(part, NB);
    chunk_scan_kernel<<<NB, 256>>>(cnt, part, off, cursor, n);
    fill_kernel<<<egrid, 256>>>(ei, nE, cursor, dinv, srcs, nrm);

    // --- layer 1 ---
    gemm128_kernel<<<gemm_grid, 256>>>(x, W1, bufA, n);
    aggregate_ln_relu_kernel<<<warp_grid, 256>>>(bufA, off, cnt, srcs, nrm, dinv,
                                                 b1, gamma, beta, bufB, n);
    // --- layer 2 ---
    gemm128_kernel<<<gemm_grid, 256>>>(bufB, W2, bufA, n);
    aggregate_ln_relu_kernel<<<warp_grid, 256>>>(bufA, off, cnt, srcs, nrm, dinv,
                                                 b2, gamma, beta, bufB, n);
    // --- layer 3 ---
    gemv3_kernel<<<warp_grid, 256>>>(bufB, W3, h3, n);
    gather3_kernel<<<ngrid, 256>>>(h3, off, cnt, srcs, nrm, dinv, b3, out, n);
}

// round 6
// speedup vs baseline: 1.1684x; 1.1684x over previous
#include <cuda_runtime.h>
#include <cuda_bf16.h>
#include <cstdint>

#define N_NODES 50000
#define N_EDGES_MAX 600000
#define FDIM    128
#define EPS     1e-5f
#define NB      ((N_NODES + 255) / 256)

// ---------------------------------------------------------------------------
// Scratch (static device globals — no allocation allowed)
// ---------------------------------------------------------------------------
__device__ __align__(16) float g_bufA[(size_t)N_NODES * FDIM];
__device__ __align__(16) float g_bufB[(size_t)N_NODES * FDIM];
__device__ __align__(16) int   g_cnt   [N_NODES];
__device__ __align__(16) int   g_off   [N_NODES];
__device__ __align__(16) int   g_cursor[N_NODES];
__device__ __align__(16) int   g_part  [256];
__device__ __align__(16) float g_dinv  [N_NODES];
__device__ __align__(16) float g_h3    [N_NODES];
__device__ __align__(16) int   g_srcs  [N_EDGES_MAX];
__device__ __align__(16) float g_nrm   [N_EDGES_MAX];

// ---------------------------------------------------------------------------
__global__ void zero_int_kernel(int* __restrict__ p, int n) {
    int i = blockIdx.x * blockDim.x + threadIdx.x;
    if (i < n) p[i] = 0;
}

__global__ void count_deg_kernel(const int* __restrict__ ei, int nE,
                                 int* __restrict__ cnt) {
    int e = blockIdx.x * blockDim.x + threadIdx.x;
    if (e >= nE) return;
    atomicAdd(&cnt[ei[nE + e]], 1);
}

__global__ void dinv_kernel(const int* __restrict__ cnt, float* __restrict__ dinv, int n) {
    int i = blockIdx.x * blockDim.x + threadIdx.x;
    if (i < n) dinv[i] = rsqrtf((float)cnt[i] + 1.0f);
}

// ---------------------------------------------------------------------------
// Exclusive scan of cnt -> off
// ---------------------------------------------------------------------------
__global__ void partial_sum_kernel(const int* __restrict__ cnt, int* __restrict__ part, int n) {
    __shared__ int s[256];
    int t = threadIdx.x;
    int i = blockIdx.x * 256 + t;
    s[t] = (i < n) ? cnt[i] : 0;
    __syncthreads();
    for (int d = 128; d > 0; d >>= 1) {
        if (t < d) s[t] += s[t + d];
        __syncthreads();
    }
    if (t == 0) part[blockIdx.x] = s[0];
}

__global__ void scan_partials_kernel(int* __restrict__ part, int nb) {
    __shared__ int s[256];
    int t = threadIdx.x;
    int v = (t < nb) ? part[t] : 0;
    s[t] = v;
    __syncthreads();
    for (int d = 1; d < 256; d <<= 1) {
        int u = (t >= d) ? s[t - d] : 0;
        __syncthreads();
        s[t] += u;
        __syncthreads();
    }
    if (t < nb) part[t] = s[t] - v;
}

__global__ void chunk_scan_kernel(const int* __restrict__ cnt, const int* __restrict__ part,
                                  int* __restrict__ off, int* __restrict__ cursor, int n) {
    __shared__ int s[256];
    int t = threadIdx.x;
    int i = blockIdx.x * 256 + t;
    int c = (i < n) ? cnt[i] : 0;
    s[t] = c;
    __syncthreads();
    for (int d = 1; d < 256; d <<= 1) {
        int u = (t >= d) ? s[t - d] : 0;
        __syncthreads();
        s[t] += u;
        __syncthreads();
    }
    if (i < n) {
        int o = part[blockIdx.x] + s[t] - c;
        off[i] = o;
        cursor[i] = o;
    }
}

__global__ void fill_kernel(const int* __restrict__ ei, int nE,
                            int* __restrict__ cursor, const float* __restrict__ dinv,
                            int* __restrict__ srcs, float* __restrict__ nrm) {
    int e = blockIdx.x * blockDim.x + threadIdx.x;
    if (e >= nE) return;
    int src = ei[e];
    int dst = ei[nE + e];
    int pos = atomicAdd(&cursor[dst], 1);
    srcs[pos] = src;
    nrm[pos]  = dinv[src] * dinv[dst];
}

// ---------------------------------------------------------------------------
// tf32 tensor-core GEMM: C[M,128] = A[M,128] @ W[128,128]
// Block: 256 threads = 8 warps x 16 rows = 128-row tile. N in two 64-halves.
// W tile in smem as tf32 bits, row-major [128][72] (pad -> conflict-free).
// ---------------------------------------------------------------------------
__device__ __forceinline__ uint32_t f2tf32(float f) {
    uint32_t r;
    asm("cvt.rna.tf32.f32 %0, %1;" : "=r"(r) : "f"(f));
    return r;
}

__device__ __forceinline__ void mma_tf32(float& c0, float& c1, float& c2, float& c3,
                                         uint32_t a0, uint32_t a1, uint32_t a2, uint32_t a3,
                                         uint32_t b0, uint32_t b1) {
    asm volatile("mma.sync.aligned.m16n8k8.row.col.f32.tf32.tf32.f32 "
                 "{%0,%1,%2,%3}, {%4,%5,%6,%7}, {%8,%9}, {%0,%1,%2,%3};"
                 : "+f"(c0), "+f"(c1), "+f"(c2), "+f"(c3)
                 : "r"(a0), "r"(a1), "r"(a2), "r"(a3), "r"(b0), "r"(b1));
}

#define WPAD 72

__global__ __launch_bounds__(256)
void gemm_tf32_kernel(const float* __restrict__ A, const float* __restrict__ W,
                      float* __restrict__ C, int M) {
    __shared__ uint32_t sw[128 * WPAD];   // 36.9 KB

    const int tid  = threadIdx.x;
    const int wid  = tid >> 5;
    const int lane = tid & 31;
    const int g    = lane >> 2;   // group id 0..7
    const int t    = lane & 3;    // thread-in-group 0..3
    const int rA   = blockIdx.x * 128 + wid * 16 + g;   // base row (and rA+8)
    const bool g0  = rA < M;
    const bool g1  = (rA + 8) < M;

    float acc[16][4];
    #pragma unroll
    for (int i = 0; i < 16; i++)
        #pragma unroll
        for (int j = 0; j < 4; j++) acc[i][j] = 0.f;

    for (int nh = 0; nh < 2; nh++) {
        __syncthreads();
        // fill smem with tf32(W[:, nh*64 .. nh*64+63]): 128 rows x 16 float4
        for (int f = tid; f < 2048; f += 256) {
            int k  = f >> 4;
            int n4 = (f & 15) * 4;
            float4 v = *(const float4*)(W + k * FDIM + nh * 64 + n4);
            uint32_t* d = &sw[k * WPAD + n4];
            d[0] = f2tf32(v.x); d[1] = f2tf32(v.y);
            d[2] = f2tf32(v.z); d[3] = f2tf32(v.w);
        }
        __syncthreads();

        #pragma unroll 4
        for (int kt = 0; kt < 16; kt++) {
            int col = kt * 8 + t;
            uint32_t a0 = g0 ? f2tf32(__ldg(A + (size_t)rA * FDIM + col))           : 0u;
            uint32_t a1 = g1 ? f2tf32(__ldg(A + (size_t)(rA + 8) * FDIM + col))     : 0u;
            uint32_t a2 = g0 ? f2tf32(__ldg(A + (size_t)rA * FDIM + col + 4))       : 0u;
            uint32_t a3 = g1 ? f2tf32(__ldg(A + (size_t)(rA + 8) * FDIM + col + 4)) : 0u;

            #pragma unroll
            for (int nt = 0; nt < 8; nt++) {
                uint32_t b0 = sw[(kt * 8 + t) * WPAD + nt * 8 + g];
                uint32_t b1 = sw[(kt * 8 + t + 4) * WPAD + nt * 8 + g];
                int ai = nh * 8 + nt;
                mma_tf32(acc[ai][0], acc[ai][1], acc[ai][2], acc[ai][3],
                         a0, a1, a2, a3, b0, b1);
            }
        }
    }

    // epilogue: acc[i] covers global cols i*8 + 2t (+1), rows rA / rA+8
    #pragma unroll
    for (int i = 0; i < 16; i++) {
        int cc = i * 8 + 2 * t;
        if (g0) *(float2*)(C + (size_t)rA * FDIM + cc)       = make_float2(acc[i][0], acc[i][1]);
        if (g1) *(float2*)(C + (size_t)(rA + 8) * FDIM + cc) = make_float2(acc[i][2], acc[i][3]);
    }
}

// ---------------------------------------------------------------------------
// Fused CSR gather + self-loop + bias + LayerNorm + ReLU. Warp per node.
// ---------------------------------------------------------------------------
__global__ __launch_bounds__(256)
void aggregate_ln_relu_kernel(const float* __restrict__ h,
                              const int* __restrict__ off, const int* __restrict__ cnt,
                              const int* __restrict__ srcs, const float* __restrict__ nrm,
                              const float* __restrict__ dinv, const float* __restrict__ bias,
                              const float* __restrict__ gamma, const float* __restrict__ beta,
                              float* __restrict__ out, int n) {
    int node = (blockIdx.x * blockDim.x + threadIdx.x) >> 5;
    int lane = threadIdx.x & 31;
    if (node >= n) return;

    float di = dinv[node];
    float d2 = di * di;

    float4 acc = *((const float4*)(h + (size_t)node * FDIM) + lane);
    acc.x *= d2; acc.y *= d2; acc.z *= d2; acc.w *= d2;

    int start = off[node];
    int m     = cnt[node];
    for (int base = 0; base < m; base += 32) {
        int k = min(32, m - base);
        int   s  = 0;
        float nm = 0.f;
        if (lane < k) {
            s  = srcs[start + base + lane];
            nm = nrm [start + base + lane];
        }
        for (int j = 0; j < k; j++) {
            int   sj = __shfl_sync(0xFFFFFFFFu, s,  j);
            float nj = __shfl_sync(0xFFFFFFFFu, nm, j);
            float4 v = *((const float4*)(h + (size_t)sj * FDIM) + lane);
            acc.x += v.x * nj; acc.y += v.y * nj;
            acc.z += v.z * nj; acc.w += v.w * nj;
        }
    }

    float4 bv = *((const float4*)bias + lane);
    acc.x += bv.x; acc.y += bv.y; acc.z += bv.z; acc.w += bv.w;

    float sum = acc.x + acc.y + acc.z + acc.w;
    #pragma unroll
    for (int o = 16; o; o >>= 1) sum += __shfl_xor_sync(0xFFFFFFFFu, sum, o);
    float mu = sum * (1.0f / FDIM);

    float tx = acc.x - mu, ty = acc.y - mu, tz = acc.z - mu, tw = acc.w - mu;
    float q = tx * tx + ty * ty + tz * tz + tw * tw;
    #pragma unroll
    for (int o = 16; o; o >>= 1) q += __shfl_xor_sync(0xFFFFFFFFu, q, o);
    float rstd = rsqrtf(q * (1.0f / FDIM) + EPS);

    float4 gv = *((const float4*)gamma + lane);
    float4 be = *((const float4*)beta  + lane);

    float4 o4;
    o4.x = fmaxf(tx * rstd * gv.x + be.x, 0.f);
    o4.y = fmaxf(ty * rstd * gv.y + be.y, 0.f);
    o4.z = fmaxf(tz * rstd * gv.z + be.z, 0.f);
    o4.w = fmaxf(tw * rstd * gv.w + be.w, 0.f);

    *((float4*)(out + (size_t)node * FDIM) + lane) = o4;
}

// ---------------------------------------------------------------------------
// Layer 3: h3 = X @ W3 (128 -> 1). Warp per node.
// ---------------------------------------------------------------------------
__global__ __launch_bounds__(256)
void gemv3_kernel(const float* __restrict__ X, const float* __restrict__ W3,
                  float* __restrict__ h3, int n) {
    int node = (blockIdx.x * blockDim.x + threadIdx.x) >> 5;
    int lane = threadIdx.x & 31;
    if (node >= n) return;
    float4 a = *((const float4*)(X + (size_t)node * FDIM) + lane);
    float4 w = *((const float4*)W3 + lane);
    float s = a.x * w.x + a.y * w.y + a.z * w.z + a.w * w.w;
    #pragma unroll
    for (int o = 16; o; o >>= 1) s += __shfl_xor_sync(0xFFFFFFFFu, s, o);
    if (lane == 0) h3[node] = s;
}

__global__ void gather3_kernel(const float* __restrict__ h3,
                               const int* __restrict__ off, const int* __restrict__ cnt,
                               const int* __restrict__ srcs, const float* __restrict__ nrm,
                               const float* __restrict__ dinv, const float* __restrict__ b3,
                               float* __restrict__ out, int n) {
    int i = blockIdx.x * blockDim.x + threadIdx.x;
    if (i >= n) return;
    float di = dinv[i];
    float acc = h3[i] * di * di;
    int start = off[i], m = cnt[i];
    for (int e = 0; e < m; e++)
        acc += h3[srcs[start + e]] * nrm[start + e];
    out[i] = acc + b3[0];
}

// ---------------------------------------------------------------------------
// Launch  (layer-1 GEMM placed as 6th launch so ncu -s 5 -c 1 captures it)
// ---------------------------------------------------------------------------
extern "C" void kernel_launch(void* const* d_in, const int* in_sizes, int n_in,
                              void* d_out, int out_size) {
    const float* x     = (const float*)d_in[0];
    const int*   ei    = (const int*)d_in[1];     // int64 marshaled to int32
    const float* W1    = (const float*)d_in[2];
    const float* b1    = (const float*)d_in[3];
    const float* W2    = (const float*)d_in[4];
    const float* b2    = (const float*)d_in[5];
    const float* W3    = (const float*)d_in[6];
    const float* b3    = (const float*)d_in[7];
    const float* gamma = (const float*)d_in[8];
    const float* beta  = (const float*)d_in[9];
    float*       out   = (float*)d_out;

    const int nE = in_sizes[1] / 2;
    const int n  = N_NODES;

    float *bufA, *bufB, *dinv, *h3, *nrm;
    int   *cnt, *off, *cursor, *part, *srcs;
    cudaGetSymbolAddress((void**)&bufA,   g_bufA);
    cudaGetSymbolAddress((void**)&bufB,   g_bufB);
    cudaGetSymbolAddress((void**)&cnt,    g_cnt);
    cudaGetSymbolAddress((void**)&off,    g_off);
    cudaGetSymbolAddress((void**)&cursor, g_cursor);
    cudaGetSymbolAddress((void**)&part,   g_part);
    cudaGetSymbolAddress((void**)&dinv,   g_dinv);
    cudaGetSymbolAddress((void**)&h3,     g_h3);
    cudaGetSymbolAddress((void**)&srcs,   g_srcs);
    cudaGetSymbolAddress((void**)&nrm,    g_nrm);

    const int egrid = (nE + 255) / 256;
    const int ngrid = (n + 255) / 256;
    const int warp_grid = (n * 32 + 255) / 256;
    const int gemm_grid = (n + 127) / 128;

    // --- CSR build (first 5 launches) + layer-1 GEMM as launch #6 ---
    zero_int_kernel<<<ngrid, 256>>>(cnt, n);
    count_deg_kernel<<<egrid, 256>>>(ei, nE, cnt);
    dinv_kernel<<<ngrid, 256>>>(cnt, dinv, n);
    partial_sum_kernel<<<NB, 256>>>(cnt, part, n);
    scan_partials_kernel<<<1, 256>>>(part, NB);

    gemm_tf32_kernel<<<gemm_grid, 256>>>(x, W1, bufA, n);      // launch #6

    chunk_scan_kernel<<<NB, 256>>>(cnt, part, off, cursor, n);
    fill_kernel<<<egrid, 256>>>(ei, nE, cursor, dinv, srcs, nrm);

    // --- layer 1 aggregate ---
    aggregate_ln_relu_kernel<<<warp_grid, 256>>>(bufA, off, cnt, srcs, nrm, dinv,
                                                 b1, gamma, beta, bufB, n);
    // --- layer 2 ---
    gemm_tf32_kernel<<<gemm_grid, 256>>>(bufB, W2, bufA, n);
    aggregate_ln_relu_kernel<<<warp_grid, 256>>>(bufA, off, cnt, srcs, nrm, dinv,
                                                 b2, gamma, beta, bufB, n);
    // --- layer 3 ---
    gemv3_kernel<<<warp_grid, 256>>>(bufB, W3, h3, n);
    gather3_kernel<<<ngrid, 256>>>(h3, off, cnt, srcs, nrm, dinv, b3, out, n);
}

// round 8
// speedup vs baseline: 1.6093x; 1.3773x over previous
#include <cuda_runtime.h>
#include <cuda_fp16.h>
#include <cstdint>

#define N_NODES 50000
#define N_EDGES_MAX 600000
#define FDIM    128
#define EPS     1e-5f
#define NB      ((N_NODES + 255) / 256)

// ---------------------------------------------------------------------------
// Scratch (static device globals — no allocation allowed)
// ---------------------------------------------------------------------------
__device__ __align__(16) __half g_xh  [(size_t)N_NODES * FDIM];
__device__ __align__(16) __half g_bufA[(size_t)N_NODES * FDIM];
__device__ __align__(16) __half g_bufB[(size_t)N_NODES * FDIM];
__device__ __align__(16) __half g_w1t [FDIM * FDIM];
__device__ __align__(16) __half g_w2t [FDIM * FDIM];
__device__ __align__(16) int    g_cnt   [N_NODES];
__device__ __align__(16) int    g_off   [N_NODES];
__device__ __align__(16) int    g_cursor[N_NODES];
__device__ __align__(16) int    g_part  [256];
__device__ __align__(16) float  g_dinv  [N_NODES];
__device__ __align__(16) float  g_h3    [N_NODES];
__device__ __align__(16) int    g_srcs  [N_EDGES_MAX];
__device__ __align__(16) float  g_nrm   [N_EDGES_MAX];

// ---------------------------------------------------------------------------
// Converts
// ---------------------------------------------------------------------------
__global__ void cvt_x_kernel(const float* __restrict__ x, __half* __restrict__ xh, int n4) {
    int i = blockIdx.x * blockDim.x + threadIdx.x;
    int stride = gridDim.x * blockDim.x;
    for (; i < n4; i += stride) {
        float4 v = ((const float4*)x)[i];
        __half2* d = (__half2*)xh + 2 * i;
        d[0] = __floats2half2_rn(v.x, v.y);
        d[1] = __floats2half2_rn(v.z, v.w);
    }
}

// Transpose W1,W2 (fp32 [k][n]) -> fp16 [n][k]
__global__ void cvt_w_kernel(const float* __restrict__ W1, const float* __restrict__ W2,
                             __half* __restrict__ Wt1, __half* __restrict__ Wt2) {
    int idx = blockIdx.x * blockDim.x + threadIdx.x;
    if (idx >= FDIM * FDIM) return;
    int k = idx >> 7, n = idx & 127;
    Wt1[n * FDIM + k] = __float2half_rn(W1[idx]);
    Wt2[n * FDIM + k] = __float2half_rn(W2[idx]);
}

// ---------------------------------------------------------------------------
// CSR build
// ---------------------------------------------------------------------------
__global__ void zero_int_kernel(int* __restrict__ p, int n) {
    int i = blockIdx.x * blockDim.x + threadIdx.x;
    if (i < n) p[i] = 0;
}

__global__ void count_deg_kernel(const int* __restrict__ ei, int nE,
                                 int* __restrict__ cnt) {
    int e = blockIdx.x * blockDim.x + threadIdx.x;
    if (e >= nE) return;
    atomicAdd(&cnt[ei[nE + e]], 1);
}

// per-block sums of cnt AND dinv computation (fused)
__global__ void partial_dinv_kernel(const int* __restrict__ cnt, int* __restrict__ part,
                                    float* __restrict__ dinv, int n) {
    __shared__ int s[256];
    int t = threadIdx.x;
    int i = blockIdx.x * 256 + t;
    int c = (i < n) ? cnt[i] : 0;
    if (i < n) dinv[i] = rsqrtf((float)c + 1.0f);
    s[t] = c;
    __syncthreads();
    for (int d = 128; d > 0; d >>= 1) {
        if (t < d) s[t] += s[t + d];
        __syncthreads();
    }
    if (t == 0) part[blockIdx.x] = s[0];
}

__global__ void scan_partials_kernel(int* __restrict__ part, int nb) {
    __shared__ int s[256];
    int t = threadIdx.x;
    int v = (t < nb) ? part[t] : 0;
    s[t] = v;
    __syncthreads();
    for (int d = 1; d < 256; d <<= 1) {
        int u = (t >= d) ? s[t - d] : 0;
        __syncthreads();
        s[t] += u;
        __syncthreads();
    }
    if (t < nb) part[t] = s[t] - v;
}

__global__ void chunk_scan_kernel(const int* __restrict__ cnt, const int* __restrict__ part,
                                  int* __restrict__ off, int* __restrict__ cursor, int n) {
    __shared__ int s[256];
    int t = threadIdx.x;
    int i = blockIdx.x * 256 + t;
    int c = (i < n) ? cnt[i] : 0;
    s[t] = c;
    __syncthreads();
    for (int d = 1; d < 256; d <<= 1) {
        int u = (t >= d) ? s[t - d] : 0;
        __syncthreads();
        s[t] += u;
        __syncthreads();
    }
    if (i < n) {
        int o = part[blockIdx.x] + s[t] - c;
        off[i] = o;
        cursor[i] = o;
    }
}

__global__ void fill_kernel(const int* __restrict__ ei, int nE,
                            int* __restrict__ cursor, const float* __restrict__ dinv,
                            int* __restrict__ srcs, float* __restrict__ nrm) {
    int e = blockIdx.x * blockDim.x + threadIdx.x;
    if (e >= nE) return;
    int src = ei[e];
    int dst = ei[nE + e];
    int pos = atomicAdd(&cursor[dst], 1);
    srcs[pos] = src;
    nrm[pos]  = dinv[src] * dinv[dst];
}

// ---------------------------------------------------------------------------
// fp16 HMMA GEMM: C[M,128] = A[M,128] @ W[128,128], all fp16 storage, fp32 acc.
// Wt is W transposed to [n][k] fp16. Block 256 thr = 8 warps x m16 = 128 rows.
// smem tiles [128][36] uint32 (pad 36 -> LDS bank = 4g+t, conflict-free).
// ---------------------------------------------------------------------------
__device__ __forceinline__ void mma_f16(float* c,
                                        uint32_t a0, uint32_t a1, uint32_t a2, uint32_t a3,
                                        uint32_t b0, uint32_t b1) {
    asm volatile("mma.sync.aligned.m16n8k16.row.col.f32.f16.f16.f32 "
                 "{%0,%1,%2,%3}, {%4,%5,%6,%7}, {%8,%9}, {%0,%1,%2,%3};"
                 : "+f"(c[0]), "+f"(c[1]), "+f"(c[2]), "+f"(c[3])
                 : "r"(a0), "r"(a1), "r"(a2), "r"(a3), "r"(b0), "r"(b1));
}

__global__ __launch_bounds__(256)
void gemm_f16_kernel(const __half* __restrict__ Ah, const __half* __restrict__ Wt,
                     __half* __restrict__ C, int M) {
    __shared__ uint32_t sA[128][36];
    __shared__ uint32_t sB[128][36];

    const int tid  = threadIdx.x;
    const int wid  = tid >> 5;
    const int lane = tid & 31;
    const int g    = lane >> 2;
    const int t    = lane & 3;
    const int row0 = blockIdx.x * 128;
    const int wr   = wid * 16;

    float acc[16][4];
    #pragma unroll
    for (int i = 0; i < 16; i++)
        #pragma unroll
        for (int j = 0; j < 4; j++) acc[i][j] = 0.f;

    for (int kh = 0; kh < 2; kh++) {
        __syncthreads();
        // A and Wt half-K tiles: 128 rows x 64 halves = 1024 uint4 each
        #pragma unroll
        for (int i = 0; i < 4; i++) {
            int f   = tid + i * 256;
            int r   = f >> 3;
            int seg = f & 7;
            uint4 va = make_uint4(0u, 0u, 0u, 0u);
            if (row0 + r < M)
                va = *(const uint4*)(Ah + (size_t)(row0 + r) * FDIM + kh * 64 + seg * 8);
            *(uint4*)&sA[r][seg * 4] = va;
            uint4 vb = *(const uint4*)(Wt + (size_t)r * FDIM + kh * 64 + seg * 8);
            *(uint4*)&sB[r][seg * 4] = vb;
        }
        __syncthreads();

        #pragma unroll
        for (int kt = 0; kt < 4; kt++) {
            uint32_t a0 = sA[wr + g    ][kt * 8 + t];
            uint32_t a1 = sA[wr + g + 8][kt * 8 + t];
            uint32_t a2 = sA[wr + g    ][kt * 8 + t + 4];
            uint32_t a3 = sA[wr + g + 8][kt * 8 + t + 4];
            #pragma unroll
            for (int nt = 0; nt < 16; nt++) {
                uint32_t b0 = sB[nt * 8 + g][kt * 8 + t];
                uint32_t b1 = sB[nt * 8 + g][kt * 8 + t + 4];
                mma_f16(acc[nt], a0, a1, a2, a3, b0, b1);
            }
        }
    }

    const int rA = row0 + wr + g;
    const bool g0 = rA < M;
    const bool g1 = (rA + 8) < M;
    #pragma unroll
    for (int nt = 0; nt < 16; nt++) {
        int cc = nt * 8 + 2 * t;
        if (g0) {
            __half2 h = __floats2half2_rn(acc[nt][0], acc[nt][1]);
            *(__half2*)(C + (size_t)rA * FDIM + cc) = h;
        }
        if (g1) {
            __half2 h = __floats2half2_rn(acc[nt][2], acc[nt][3]);
            *(__half2*)(C + (size_t)(rA + 8) * FDIM + cc) = h;
        }
    }
}

// ---------------------------------------------------------------------------
// Fused CSR gather + self-loop + bias + LayerNorm + ReLU. Warp per node.
// fp16 features in/out, fp32 math.
// ---------------------------------------------------------------------------
__global__ __launch_bounds__(256)
void aggregate_ln_relu_kernel(const __half* __restrict__ h,
                              const int* __restrict__ off, const int* __restrict__ cnt,
                              const int* __restrict__ srcs, const float* __restrict__ nrm,
                              const float* __restrict__ dinv, const float* __restrict__ bias,
                              const float* __restrict__ gamma, const float* __restrict__ beta,
                              __half* __restrict__ out, int n) {
    int node = (blockIdx.x * blockDim.x + threadIdx.x) >> 5;
    int lane = threadIdx.x & 31;
    if (node >= n) return;

    float di = dinv[node];
    float d2 = di * di;

    // self-loop term: own row
    uint2 u = *((const uint2*)(h + (size_t)node * FDIM) + lane);
    float2 f0 = __half22float2(*(__half2*)&u.x);
    float2 f1 = __half22float2(*(__half2*)&u.y);
    float ax = f0.x * d2, ay = f0.y * d2, az = f1.x * d2, aw = f1.y * d2;

    int start = off[node];
    int m     = cnt[node];
    for (int base = 0; base < m; base += 32) {
        int k = min(32, m - base);
        int   s  = 0;
        float nm = 0.f;
        if (lane < k) {
            s  = srcs[start + base + lane];
            nm = nrm [start + base + lane];
        }
        for (int j = 0; j < k; j++) {
            int   sj = __shfl_sync(0xFFFFFFFFu, s,  j);
            float nj = __shfl_sync(0xFFFFFFFFu, nm, j);
            uint2 v = *((const uint2*)(h + (size_t)sj * FDIM) + lane);
            float2 v0 = __half22float2(*(__half2*)&v.x);
            float2 v1 = __half22float2(*(__half2*)&v.y);
            ax += v0.x * nj; ay += v0.y * nj;
            az += v1.x * nj; aw += v1.y * nj;
        }
    }

    float4 bv = *((const float4*)bias + lane);
    ax += bv.x; ay += bv.y; az += bv.z; aw += bv.w;

    float sum = ax + ay + az + aw;
    #pragma unroll
    for (int o = 16; o; o >>= 1) sum += __shfl_xor_sync(0xFFFFFFFFu, sum, o);
    float mu = sum * (1.0f / FDIM);

    float tx = ax - mu, ty = ay - mu, tz = az - mu, tw = aw - mu;
    float q = tx * tx + ty * ty + tz * tz + tw * tw;
    #pragma unroll
    for (int o = 16; o; o >>= 1) q += __shfl_xor_sync(0xFFFFFFFFu, q, o);
    float rstd = rsqrtf(q * (1.0f / FDIM) + EPS);

    float4 gv = *((const float4*)gamma + lane);
    float4 be = *((const float4*)beta  + lane);

    float ox = fmaxf(tx * rstd * gv.x + be.x, 0.f);
    float oy = fmaxf(ty * rstd * gv.y + be.y, 0.f);
    float oz = fmaxf(tz * rstd * gv.z + be.z, 0.f);
    float ow = fmaxf(tw * rstd * gv.w + be.w, 0.f);

    uint2 r;
    *(__half2*)&r.x = __floats2half2_rn(ox, oy);
    *(__half2*)&r.y = __floats2half2_rn(oz, ow);
    *((uint2*)(out + (size_t)node * FDIM) + lane) = r;
}

// ---------------------------------------------------------------------------
// Layer 3: h3 = X @ W3 (128 -> 1). Warp per node, fp16 X.
// ---------------------------------------------------------------------------
__global__ __launch_bounds__(256)
void gemv3_kernel(const __half* __restrict__ X, const float* __restrict__ W3,
                  float* __restrict__ h3, int n) {
    int node = (blockIdx.x * blockDim.x + threadIdx.x) >> 5;
    int lane = threadIdx.x & 31;
    if (node >= n) return;
    uint2 u = *((const uint2*)(X + (size_t)node * FDIM) + lane);
    float2 f0 = __half22float2(*(__half2*)&u.x);
    float2 f1 = __half22float2(*(__half2*)&u.y);
    float4 w = *((const float4*)W3 + lane);
    float s = f0.x * w.x + f0.y * w.y + f1.x * w.z + f1.y * w.w;
    #pragma unroll
    for (int o = 16; o; o >>= 1) s += __shfl_xor_sync(0xFFFFFFFFu, s, o);
    if (lane == 0) h3[node] = s;
}

__global__ void gather3_kernel(const float* __restrict__ h3,
                               const int* __restrict__ off, const int* __restrict__ cnt,
                               const int* __restrict__ srcs, const float* __restrict__ nrm,
                               const float* __restrict__ dinv, const float* __restrict__ b3,
                               float* __restrict__ out, int n) {
    int i = blockIdx.x * blockDim.x + threadIdx.x;
    if (i >= n) return;
    float di = dinv[i];
    float acc = h3[i] * di * di;
    int start = off[i], m = cnt[i];
    for (int e = 0; e < m; e++)
        acc += h3[srcs[start + e]] * nrm[start + e];
    out[i] = acc + b3[0];
}

// ---------------------------------------------------------------------------
// Launch (gemm1 is the 4th user kernel -> captured by ncu -s 5 -c 1)
// ---------------------------------------------------------------------------
extern "C" void kernel_launch(void* const* d_in, const int* in_sizes, int n_in,
                              void* d_out, int out_size) {
    const float* x     = (const float*)d_in[0];
    const int*   ei    = (const int*)d_in[1];
    const float* W1    = (const float*)d_in[2];
    const float* b1    = (const float*)d_in[3];
    const float* W2    = (const float*)d_in[4];
    const float* b2    = (const float*)d_in[5];
    const float* W3    = (const float*)d_in[6];
    const float* b3    = (const float*)d_in[7];
    const float* gamma = (const float*)d_in[8];
    const float* beta  = (const float*)d_in[9];
    float*       out   = (float*)d_out;

    const int nE = in_sizes[1] / 2;
    const int n  = N_NODES;

    __half *xh, *bufA, *bufB, *w1t, *w2t;
    float  *dinv, *h3, *nrm;
    int    *cnt, *off, *cursor, *part, *srcs;
    cudaGetSymbolAddress((void**)&xh,     g_xh);
    cudaGetSymbolAddress((void**)&bufA,   g_bufA);
    cudaGetSymbolAddress((void**)&bufB,   g_bufB);
    cudaGetSymbolAddress((void**)&w1t,    g_w1t);
    cudaGetSymbolAddress((void**)&w2t,    g_w2t);
    cudaGetSymbolAddress((void**)&cnt,    g_cnt);
    cudaGetSymbolAddress((void**)&off,    g_off);
    cudaGetSymbolAddress((void**)&cursor, g_cursor);
    cudaGetSymbolAddress((void**)&part,   g_part);
    cudaGetSymbolAddress((void**)&dinv,   g_dinv);
    cudaGetSymbolAddress((void**)&h3,     g_h3);
    cudaGetSymbolAddress((void**)&srcs,   g_srcs);
    cudaGetSymbolAddress((void**)&nrm,    g_nrm);

    const int egrid = (nE + 255) / 256;
    const int ngrid = (n + 255) / 256;
    const int warp_grid = (n * 32 + 255) / 256;
    const int gemm_grid = (n + 127) / 128;

    // 1-3: converts + zero (independent)
    cvt_x_kernel<<<1024, 256>>>(x, xh, n * FDIM / 4);
    cvt_w_kernel<<<(FDIM * FDIM + 255) / 256, 256>>>(W1, W2, w1t, w2t);
    zero_int_kernel<<<ngrid, 256>>>(cnt, n);

    // 4: layer-1 GEMM (profiled next round)
    gemm_f16_kernel<<<gemm_grid, 256>>>(xh, w1t, bufA, n);

    // 5-9: CSR build
    count_deg_kernel<<<egrid, 256>>>(ei, nE, cnt);
    partial_dinv_kernel<<<NB, 256>>>(cnt, part, dinv, n);
    scan_partials_kernel<<<1, 256>>>(part, NB);
    chunk_scan_kernel<<<NB, 256>>>(cnt, part, off, cursor, n);
    fill_kernel<<<egrid, 256>>>(ei, nE, cursor, dinv, srcs, nrm);

    // 10: layer-1 aggregate
    aggregate_ln_relu_kernel<<<warp_grid, 256>>>(bufA, off, cnt, srcs, nrm, dinv,
                                                 b1, gamma, beta, bufB, n);
    // 11-12: layer 2
    gemm_f16_kernel<<<gemm_grid, 256>>>(bufB, w2t, bufA, n);
    aggregate_ln_relu_kernel<<<warp_grid, 256>>>(bufA, off, cnt, srcs, nrm, dinv,
                                                 b2, gamma, beta, bufB, n);
    // 13-14: layer 3
    gemv3_kernel<<<warp_grid, 256>>>(bufB, W3, h3, n);
    gather3_kernel<<<ngrid, 256>>>(h3, off, cnt, srcs, nrm, dinv, b3, out, n);
}

// round 13
// speedup vs baseline: 1.6133x; 1.0025x over previous
#include <cuda_runtime.h>
#include <cuda_fp16.h>
#include <cstdint>

#define N_NODES 50000
#define N_EDGES_MAX 600000
#define FDIM    128
#define EPS     1e-5f
#define NB      ((N_NODES + 255) / 256)

// ---------------------------------------------------------------------------
// Scratch (static device globals — no allocation allowed)
// ---------------------------------------------------------------------------
__device__ __align__(16) __half g_xh  [(size_t)N_NODES * FDIM];
__device__ __align__(16) __half g_bufA[(size_t)N_NODES * FDIM];
__device__ __align__(16) __half g_bufB[(size_t)N_NODES * FDIM];
__device__ __align__(16) __half g_w1t [FDIM * FDIM];
__device__ __align__(16) __half g_w2t [FDIM * FDIM];
__device__ __align__(16) int    g_cnt   [N_NODES];
__device__ __align__(16) int    g_off   [N_NODES];
__device__ __align__(16) int    g_cursor[N_NODES];
__device__ __align__(16) int    g_part  [256];
__device__ __align__(16) float  g_dinv  [N_NODES];
__device__ __align__(16) float  g_h3    [N_NODES];
__device__ __align__(16) int2   g_recs  [N_EDGES_MAX];   // {src, nrm bits}

// ---------------------------------------------------------------------------
// Converts
// ---------------------------------------------------------------------------
__global__ void cvt_x_kernel(const float* __restrict__ x, __half* __restrict__ xh, int n4) {
    int i = blockIdx.x * blockDim.x + threadIdx.x;
    int stride = gridDim.x * blockDim.x;
    for (; i < n4; i += stride) {
        float4 v = ((const float4*)x)[i];
        __half2* d = (__half2*)xh + 2 * i;
        d[0] = __floats2half2_rn(v.x, v.y);
        d[1] = __floats2half2_rn(v.z, v.w);
    }
}

__global__ void cvt_w_kernel(const float* __restrict__ W1, const float* __restrict__ W2,
                             __half* __restrict__ Wt1, __half* __restrict__ Wt2) {
    int idx = blockIdx.x * blockDim.x + threadIdx.x;
    if (idx >= FDIM * FDIM) return;
    int k = idx >> 7, n = idx & 127;
    Wt1[n * FDIM + k] = __float2half_rn(W1[idx]);
    Wt2[n * FDIM + k] = __float2half_rn(W2[idx]);
}

// ---------------------------------------------------------------------------
// CSR build
// ---------------------------------------------------------------------------
__global__ void zero_int_kernel(int* __restrict__ p, int n) {
    int i = blockIdx.x * blockDim.x + threadIdx.x;
    if (i < n) p[i] = 0;
}

__global__ void count_deg_kernel(const int* __restrict__ ei, int nE,
                                 int* __restrict__ cnt) {
    int e = blockIdx.x * blockDim.x + threadIdx.x;
    if (e >= nE) return;
    atomicAdd(&cnt[ei[nE + e]], 1);
}

__global__ void partial_dinv_kernel(const int* __restrict__ cnt, int* __restrict__ part,
                                    float* __restrict__ dinv, int n) {
    __shared__ int s[256];
    int t = threadIdx.x;
    int i = blockIdx.x * 256 + t;
    int c = (i < n) ? cnt[i] : 0;
    if (i < n) dinv[i] = rsqrtf((float)c + 1.0f);
    s[t] = c;
    __syncthreads();
    for (int d = 128; d > 0; d >>= 1) {
        if (t < d) s[t] += s[t + d];
        __syncthreads();
    }
    if (t == 0) part[blockIdx.x] = s[0];
}

__global__ void scan_partials_kernel(int* __restrict__ part, int nb) {
    __shared__ int s[256];
    int t = threadIdx.x;
    int v = (t < nb) ? part[t] : 0;
    s[t] = v;
    __syncthreads();
    for (int d = 1; d < 256; d <<= 1) {
        int u = (t >= d) ? s[t - d] : 0;
        __syncthreads();
        s[t] += u;
        __syncthreads();
    }
    if (t < nb) part[t] = s[t] - v;
}

__global__ void chunk_scan_kernel(const int* __restrict__ cnt, const int* __restrict__ part,
                                  int* __restrict__ off, int* __restrict__ cursor, int n) {
    __shared__ int s[256];
    int t = threadIdx.x;
    int i = blockIdx.x * 256 + t;
    int c = (i < n) ? cnt[i] : 0;
    s[t] = c;
    __syncthreads();
    for (int d = 1; d < 256; d <<= 1) {
        int u = (t >= d) ? s[t - d] : 0;
        __syncthreads();
        s[t] += u;
        __syncthreads();
    }
    if (i < n) {
        int o = part[blockIdx.x] + s[t] - c;
        off[i] = o;
        cursor[i] = o;
    }
}

__global__ void fill_kernel(const int* __restrict__ ei, int nE,
                            int* __restrict__ cursor, const float* __restrict__ dinv,
                            int2* __restrict__ recs) {
    int e = blockIdx.x * blockDim.x + threadIdx.x;
    if (e >= nE) return;
    int src = ei[e];
    int dst = ei[nE + e];
    int pos = atomicAdd(&cursor[dst], 1);
    int2 r;
    r.x = src;
    r.y = __float_as_int(dinv[src] * dinv[dst]);
    recs[pos] = r;
}

// ---------------------------------------------------------------------------
// fp16 HMMA GEMM: C[M,128] = A[M,128] @ W[128,128].
// Static-smem two-half structure; fragments via ldmatrix.x4.
// Tiles [128][36] uint32: stride 36 words -> fragment rows step banks by 4
// (8 rows = 8 distinct banks, conflict-free), 144B rows keep 16B alignment.
// ---------------------------------------------------------------------------
__device__ __forceinline__ void mma_f16(float* c,
                                        uint32_t a0, uint32_t a1, uint32_t a2, uint32_t a3,
                                        uint32_t b0, uint32_t b1) {
    asm volatile("mma.sync.aligned.m16n8k16.row.col.f32.f16.f16.f32 "
                 "{%0,%1,%2,%3}, {%4,%5,%6,%7}, {%8,%9}, {%0,%1,%2,%3};"
                 : "+f"(c[0]), "+f"(c[1]), "+f"(c[2]), "+f"(c[3])
                 : "r"(a0), "r"(a1), "r"(a2), "r"(a3), "r"(b0), "r"(b1));
}

__device__ __forceinline__ void ldsm_x4(uint32_t& r0, uint32_t& r1, uint32_t& r2, uint32_t& r3,
                                        uint32_t addr) {
    asm volatile("ldmatrix.sync.aligned.m8n8.x4.shared.b16 {%0,%1,%2,%3}, [%4];"
                 : "=r"(r0), "=r"(r1), "=r"(r2), "=r"(r3) : "r"(addr));
}

__global__ __launch_bounds__(256)
void gemm_f16_kernel(const __half* __restrict__ Ah, const __half* __restrict__ Wt,
                     __half* __restrict__ C, int M) {
    __shared__ __align__(16) uint32_t sA[128][36];
    __shared__ __align__(16) uint32_t sB[128][36];

    const int tid  = threadIdx.x;
    const int wid  = tid >> 5;
    const int lane = tid & 31;
    const int g    = lane >> 2;
    const int t    = lane & 3;
    const int row0 = blockIdx.x * 128;
    const int wr   = wid * 16;

    float acc[16][4];
    #pragma unroll
    for (int i = 0; i < 16; i++)
        #pragma unroll
        for (int j = 0; j < 4; j++) acc[i][j] = 0.f;

    // per-lane ldmatrix offsets (bytes)
    const int q  = lane >> 3;        // which 8x8 matrix this lane addresses
    const int rr = lane & 7;         // row within it
    const uint32_t sA_base = (uint32_t)__cvta_generic_to_shared(&sA[0][0]);
    const uint32_t sB_base = (uint32_t)__cvta_generic_to_shared(&sB[0][0]);
    // A m16k16 fragment regs: a0=m0-7/k0-7, a1=m8-15/k0-7, a2=m0-7/k8-15, a3=m8-15/k8-15
    const uint32_t aOff = (uint32_t)(((wr + (q & 1) * 8 + rr) * 36 + (q >> 1) * 4) * 4);
    // B fragment regs: r0=n0-7/k0-7, r1=n0-7/k8-15, r2=n8-15/k0-7, r3=n8-15/k8-15
    const uint32_t bOff = (uint32_t)((((q >> 1) * 8 + rr) * 36 + (q & 1) * 4) * 4);

    for (int kh = 0; kh < 2; kh++) {
        __syncthreads();
        // stage half-K tiles: 128 rows x 32 words (64 halves); 4 uint4/thread each
        #pragma unroll
        for (int i = 0; i < 4; i++) {
            int f   = tid + i * 256;     // 0..1023
            int r   = f >> 3;            // 0..127
            int seg = f & 7;             // 0..7 (uint4 within row)
            uint4 va = make_uint4(0u, 0u, 0u, 0u);
            if (row0 + r < M)
                va = *(const uint4*)(Ah + (size_t)(row0 + r) * FDIM + kh * 64 + seg * 8);
            *(uint4*)&sA[r][seg * 4] = va;
            uint4 vb = *(const uint4*)(Wt + (size_t)r * FDIM + kh * 64 + seg * 8);
            *(uint4*)&sB[r][seg * 4] = vb;
        }
        __syncthreads();

        #pragma unroll
        for (int kt = 0; kt < 4; kt++) {
            uint32_t a0, a1, a2, a3;
            ldsm_x4(a0, a1, a2, a3, sA_base + aOff + kt * 32);
            #pragma unroll
            for (int nt2 = 0; nt2 < 8; nt2++) {
                uint32_t b00, b01, b10, b11;
                ldsm_x4(b00, b01, b10, b11,
                        sB_base + bOff + (uint32_t)(nt2 * (16 * 36 * 4)) + kt * 32);
                mma_f16(acc[2 * nt2],     a0, a1, a2, a3, b00, b01);
                mma_f16(acc[2 * nt2 + 1], a0, a1, a2, a3, b10, b11);
            }
        }
    }

    const int rA = row0 + wr + g;
    const bool g0 = rA < M;
    const bool g1 = (rA + 8) < M;
    #pragma unroll
    for (int nt = 0; nt < 16; nt++) {
        int cc = nt * 8 + 2 * t;
        if (g0) *(__half2*)(C + (size_t)rA * FDIM + cc)       = __floats2half2_rn(acc[nt][0], acc[nt][1]);
        if (g1) *(__half2*)(C + (size_t)(rA + 8) * FDIM + cc) = __floats2half2_rn(acc[nt][2], acc[nt][3]);
    }
}

// ---------------------------------------------------------------------------
// Fused CSR gather + self-loop + bias + LayerNorm + ReLU. Warp per node,
// two edges in flight (16-lane halves), uint4 feature loads, fp32 math.
// CONVERGENCE-SAFE: pair loop bound k is warp-uniform; both shuffles execute
// on all 32 lanes every iteration (clamped index); only load/acc predicated.
// ---------------------------------------------------------------------------
__global__ __launch_bounds__(256)
void aggregate_ln_relu_kernel(const __half* __restrict__ h,
                              const int* __restrict__ off, const int* __restrict__ cnt,
                              const int2* __restrict__ recs,
                              const float* __restrict__ dinv, const float* __restrict__ bias,
                              const float* __restrict__ gamma, const float* __restrict__ beta,
                              __half* __restrict__ out, int n) {
    int node = (blockIdx.x * blockDim.x + threadIdx.x) >> 5;
    int lane = threadIdx.x & 31;
    if (node >= n) return;

    const int half_id = lane >> 4;      // 0 or 1
    const int fl      = lane & 15;      // feature-chunk lane (16B each)

    float a[8];
    #pragma unroll
    for (int i = 0; i < 8; i++) a[i] = 0.f;

    int start = off[node];
    int m     = cnt[node];
    for (int base = 0; base < m; base += 32) {
        int k = min(32, m - base);
        int2 rec = make_int2(0, 0);
        if (lane < k) rec = recs[start + base + lane];
        for (int jb = 0; jb < k; jb += 2) {
            int j  = jb + half_id;
            int jj = (j < k) ? j : 0;               // clamp shuffle index
            int   sj = __shfl_sync(0xFFFFFFFFu, rec.x, jj);
            float nj = __int_as_float(__shfl_sync(0xFFFFFFFFu, rec.y, jj));
            if (j < k) {
                uint4 v = *((const uint4*)(h + (size_t)sj * FDIM) + fl);
                float2 p0 = __half22float2(*(__half2*)&v.x);
                float2 p1 = __half22float2(*(__half2*)&v.y);
                float2 p2 = __half22float2(*(__half2*)&v.z);
                float2 p3 = __half22float2(*(__half2*)&v.w);
                a[0] += p0.x * nj; a[1] += p0.y * nj;
                a[2] += p1.x * nj; a[3] += p1.y * nj;
                a[4] += p2.x * nj; a[5] += p2.y * nj;
                a[6] += p3.x * nj; a[7] += p3.y * nj;
            }
        }
    }

    // combine halves (identical feature mapping via fl)
    #pragma unroll
    for (int i = 0; i < 8; i++) a[i] += __shfl_xor_sync(0xFFFFFFFFu, a[i], 16);

    // self-loop + bias
    float di = dinv[node];
    float d2 = di * di;
    {
        uint4 v = *((const uint4*)(h + (size_t)node * FDIM) + fl);
        float2 p0 = __half22float2(*(__half2*)&v.x);
        float2 p1 = __half22float2(*(__half2*)&v.y);
        float2 p2 = __half22float2(*(__half2*)&v.z);
        float2 p3 = __half22float2(*(__half2*)&v.w);
        a[0] += p0.x * d2; a[1] += p0.y * d2;
        a[2] += p1.x * d2; a[3] += p1.y * d2;
        a[4] += p2.x * d2; a[5] += p2.y * d2;
        a[6] += p3.x * d2; a[7] += p3.y * d2;
    }
    float4 b0 = ((const float4*)bias)[2 * fl];
    float4 b1 = ((const float4*)bias)[2 * fl + 1];
    a[0] += b0.x; a[1] += b0.y; a[2] += b0.z; a[3] += b0.w;
    a[4] += b1.x; a[5] += b1.y; a[6] += b1.z; a[7] += b1.w;

    // LayerNorm (halves hold identical sums after the xor-16 combine)
    float s = a[0] + a[1] + a[2] + a[3] + a[4] + a[5] + a[6] + a[7];
    #pragma unroll
    for (int o = 8; o; o >>= 1) s += __shfl_xor_sync(0xFFFFFFFFu, s, o);
    float mu = s * (1.0f / FDIM);

    float tt[8], qv = 0.f;
    #pragma unroll
    for (int i = 0; i < 8; i++) { tt[i] = a[i] - mu; qv += tt[i] * tt[i]; }
    #pragma unroll
    for (int o = 8; o; o >>= 1) qv += __shfl_xor_sync(0xFFFFFFFFu, qv, o);
    float rstd = rsqrtf(qv * (1.0f / FDIM) + EPS);

    if (half_id == 0) {
        float4 gv0 = ((const float4*)gamma)[2 * fl];
        float4 gv1 = ((const float4*)gamma)[2 * fl + 1];
        float4 be0 = ((const float4*)beta)[2 * fl];
        float4 be1 = ((const float4*)beta)[2 * fl + 1];
        float o0 = fmaxf(tt[0] * rstd * gv0.x + be0.x, 0.f);
        float o1 = fmaxf(tt[1] * rstd * gv0.y + be0.y, 0.f);
        float o2 = fmaxf(tt[2] * rstd * gv0.z + be0.z, 0.f);
        float o3 = fmaxf(tt[3] * rstd * gv0.w + be0.w, 0.f);
        float o4 = fmaxf(tt[4] * rstd * gv1.x + be1.x, 0.f);
        float o5 = fmaxf(tt[5] * rstd * gv1.y + be1.y, 0.f);
        float o6 = fmaxf(tt[6] * rstd * gv1.z + be1.z, 0.f);
        float o7 = fmaxf(tt[7] * rstd * gv1.w + be1.w, 0.f);
        uint4 r;
        *(__half2*)&r.x = __floats2half2_rn(o0, o1);
        *(__half2*)&r.y = __floats2half2_rn(o2, o3);
        *(__half2*)&r.z = __floats2half2_rn(o4, o5);
        *(__half2*)&r.w = __floats2half2_rn(o6, o7);
        *((uint4*)(out + (size_t)node * FDIM) + fl) = r;
    }
}

// ---------------------------------------------------------------------------
// Layer 3
// ---------------------------------------------------------------------------
__global__ __launch_bounds__(256)
void gemv3_kernel(const __half* __restrict__ X, const float* __restrict__ W3,
                  float* __restrict__ h3, int n) {
    int node = (blockIdx.x * blockDim.x + threadIdx.x) >> 5;
    int lane = threadIdx.x & 31;
    if (node >= n) return;
    uint2 u = *((const uint2*)(X + (size_t)node * FDIM) + lane);
    float2 f0 = __half22float2(*(__half2*)&u.x);
    float2 f1 = __half22float2(*(__half2*)&u.y);
    float4 w = *((const float4*)W3 + lane);
    float s = f0.x * w.x + f0.y * w.y + f1.x * w.z + f1.y * w.w;
    #pragma unroll
    for (int o = 16; o; o >>= 1) s += __shfl_xor_sync(0xFFFFFFFFu, s, o);
    if (lane == 0) h3[node] = s;
}

__global__ void gather3_kernel(const float* __restrict__ h3,
                               const int* __restrict__ off, const int* __restrict__ cnt,
                               const int2* __restrict__ recs,
                               const float* __restrict__ dinv, const float* __restrict__ b3,
                               float* __restrict__ out, int n) {
    int i = blockIdx.x * blockDim.x + threadIdx.x;
    if (i >= n) return;
    float di = dinv[i];
    float acc = h3[i] * di * di;
    int start = off[i], m = cnt[i];
    for (int e = 0; e < m; e++) {
        int2 r = recs[start + e];
        acc += h3[r.x] * __int_as_float(r.y);
    }
    out[i] = acc + b3[0];
}

// ---------------------------------------------------------------------------
// Launch (gemm1 is 4th kernel -> captured by ncu window)
// ---------------------------------------------------------------------------
extern "C" void kernel_launch(void* const* d_in, const int* in_sizes, int n_in,
                              void* d_out, int out_size) {
    const float* x     = (const float*)d_in[0];
    const int*   ei    = (const int*)d_in[1];
    const float* W1    = (const float*)d_in[2];
    const float* b1    = (const float*)d_in[3];
    const float* W2    = (const float*)d_in[4];
    const float* b2    = (const float*)d_in[5];
    const float* W3    = (const float*)d_in[6];
    const float* b3    = (const float*)d_in[7];
    const float* gamma = (const float*)d_in[8];
    const float* beta  = (const float*)d_in[9];
    float*       out   = (float*)d_out;

    const int nE = in_sizes[1] / 2;
    const int n  = N_NODES;

    __half *xh, *bufA, *bufB, *w1t, *w2t;
    float  *dinv, *h3;
    int    *cnt, *off, *cursor, *part;
    int2   *recs;
    cudaGetSymbolAddress((void**)&xh,     g_xh);
    cudaGetSymbolAddress((void**)&bufA,   g_bufA);
    cudaGetSymbolAddress((void**)&bufB,   g_bufB);
    cudaGetSymbolAddress((void**)&w1t,    g_w1t);
    cudaGetSymbolAddress((void**)&w2t,    g_w2t);
    cudaGetSymbolAddress((void**)&cnt,    g_cnt);
    cudaGetSymbolAddress((void**)&off,    g_off);
    cudaGetSymbolAddress((void**)&cursor, g_cursor);
    cudaGetSymbolAddress((void**)&part,   g_part);
    cudaGetSymbolAddress((void**)&dinv,   g_dinv);
    cudaGetSymbolAddress((void**)&h3,     g_h3);
    cudaGetSymbolAddress((void**)&recs,   g_recs);

    const int egrid = (nE + 255) / 256;
    const int ngrid = (n + 255) / 256;
    const int warp_grid = (n * 32 + 255) / 256;
    const int gemm_grid = (n + 127) / 128;

    // 1-3: converts + zero
    cvt_x_kernel<<<1024, 256>>>(x, xh, n * FDIM / 4);
    cvt_w_kernel<<<(FDIM * FDIM + 255) / 256, 256>>>(W1, W2, w1t, w2t);
    zero_int_kernel<<<ngrid, 256>>>(cnt, n);

    // 4: layer-1 GEMM (profiled)
    gemm_f16_kernel<<<gemm_grid, 256>>>(xh, w1t, bufA, n);

    // 5-9: CSR build
    count_deg_kernel<<<egrid, 256>>>(ei, nE, cnt);
    partial_dinv_kernel<<<NB, 256>>>(cnt, part, dinv, n);
    scan_partials_kernel<<<1, 256>>>(part, NB);
    chunk_scan_kernel<<<NB, 256>>>(cnt, part, off, cursor, n);
    fill_kernel<<<egrid, 256>>>(ei, nE, cursor, dinv, recs);

    // 10: layer-1 aggregate
    aggregate_ln_relu_kernel<<<warp_grid, 256>>>(bufA, off, cnt, recs, dinv,
                                                 b1, gamma, beta, bufB, n);
    // 11-12: layer 2
    gemm_f16_kernel<<<gemm_grid, 256>>>(bufB, w2t, bufA, n);
    aggregate_ln_relu_kernel<<<warp_grid, 256>>>(bufA, off, cnt, recs, dinv,
                                                 b2, gamma, beta, bufB, n);
    // 13-14: layer 3
    gemv3_kernel<<<warp_grid, 256>>>(bufB, W3, h3, n);
    gather3_kernel<<<ngrid, 256>>>(h3, off, cnt, recs, dinv, b3, out, n);
}

// round 14
// speedup vs baseline: 1.6419x; 1.0178x over previous
#include <cuda_runtime.h>
#include <cuda_fp16.h>
#include <cstdint>

#define N_NODES 50000
#define N_EDGES_MAX 600000
#define FDIM    128
#define EPS     1e-5f
#define NB      ((N_NODES + 255) / 256)

// ---------------------------------------------------------------------------
// Scratch (static device globals — no allocation allowed)
// ---------------------------------------------------------------------------
__device__ __align__(16) __half g_xh  [(size_t)N_NODES * FDIM];
__device__ __align__(16) __half g_bufA[(size_t)N_NODES * FDIM];
__device__ __align__(16) __half g_bufB[(size_t)N_NODES * FDIM];
__device__ __align__(16) __half g_w1t [FDIM * FDIM];
__device__ __align__(16) __half g_w2t [FDIM * FDIM];
__device__ __align__(16) int    g_cnt   [N_NODES];
__device__ __align__(16) int    g_off   [N_NODES];
__device__ __align__(16) int    g_cursor[N_NODES];
__device__ __align__(16) int    g_part  [256];
__device__ __align__(16) float  g_dinv  [N_NODES];
__device__ __align__(16) float  g_h3    [N_NODES];
__device__ __align__(16) int2   g_recs  [N_EDGES_MAX];   // {src, nrm bits}

// ---------------------------------------------------------------------------
// Converts
// ---------------------------------------------------------------------------
__global__ void cvt_x_kernel(const float* __restrict__ x, __half* __restrict__ xh, int n4) {
    int i = blockIdx.x * blockDim.x + threadIdx.x;
    int stride = gridDim.x * blockDim.x;
    for (; i < n4; i += stride) {
        float4 v = ((const float4*)x)[i];
        __half2* d = (__half2*)xh + 2 * i;
        d[0] = __floats2half2_rn(v.x, v.y);
        d[1] = __floats2half2_rn(v.z, v.w);
    }
}

__global__ void cvt_w_kernel(const float* __restrict__ W1, const float* __restrict__ W2,
                             __half* __restrict__ Wt1, __half* __restrict__ Wt2) {
    int idx = blockIdx.x * blockDim.x + threadIdx.x;
    if (idx >= FDIM * FDIM) return;
    int k = idx >> 7, n = idx & 127;
    Wt1[n * FDIM + k] = __float2half_rn(W1[idx]);
    Wt2[n * FDIM + k] = __float2half_rn(W2[idx]);
}

// ---------------------------------------------------------------------------
// CSR build
// ---------------------------------------------------------------------------
__global__ void zero_int_kernel(int* __restrict__ p, int n) {
    int i = blockIdx.x * blockDim.x + threadIdx.x;
    if (i < n) p[i] = 0;
}

__global__ void count_deg_kernel(const int* __restrict__ ei, int nE,
                                 int* __restrict__ cnt) {
    int e = blockIdx.x * blockDim.x + threadIdx.x;
    if (e >= nE) return;
    atomicAdd(&cnt[ei[nE + e]], 1);
}

__global__ void partial_dinv_kernel(const int* __restrict__ cnt, int* __restrict__ part,
                                    float* __restrict__ dinv, int n) {
    __shared__ int s[256];
    int t = threadIdx.x;
    int i = blockIdx.x * 256 + t;
    int c = (i < n) ? cnt[i] : 0;
    if (i < n) dinv[i] = rsqrtf((float)c + 1.0f);
    s[t] = c;
    __syncthreads();
    for (int d = 128; d > 0; d >>= 1) {
        if (t < d) s[t] += s[t + d];
        __syncthreads();
    }
    if (t == 0) part[blockIdx.x] = s[0];
}

__global__ void scan_partials_kernel(int* __restrict__ part, int nb) {
    __shared__ int s[256];
    int t = threadIdx.x;
    int v = (t < nb) ? part[t] : 0;
    s[t] = v;
    __syncthreads();
    for (int d = 1; d < 256; d <<= 1) {
        int u = (t >= d) ? s[t - d] : 0;
        __syncthreads();
        s[t] += u;
        __syncthreads();
    }
    if (t < nb) part[t] = s[t] - v;
}

__global__ void chunk_scan_kernel(const int* __restrict__ cnt, const int* __restrict__ part,
                                  int* __restrict__ off, int* __restrict__ cursor, int n) {
    __shared__ int s[256];
    int t = threadIdx.x;
    int i = blockIdx.x * 256 + t;
    int c = (i < n) ? cnt[i] : 0;
    s[t] = c;
    __syncthreads();
    for (int d = 1; d < 256; d <<= 1) {
        int u = (t >= d) ? s[t - d] : 0;
        __syncthreads();
        s[t] += u;
        __syncthreads();
    }
    if (i < n) {
        int o = part[blockIdx.x] + s[t] - c;
        off[i] = o;
        cursor[i] = o;
    }
}

__global__ void fill_kernel(const int* __restrict__ ei, int nE,
                            int* __restrict__ cursor, const float* __restrict__ dinv,
                            int2* __restrict__ recs) {
    int e = blockIdx.x * blockDim.x + threadIdx.x;
    if (e >= nE) return;
    int src = ei[e];
    int dst = ei[nE + e];
    int pos = atomicAdd(&cursor[dst], 1);
    int2 r;
    r.x = src;
    r.y = __float_as_int(dinv[src] * dinv[dst]);
    recs[pos] = r;
}

// ---------------------------------------------------------------------------
// fp16 HMMA GEMM: C[M,128] = A[M,128] @ W[128,128].
// Static-smem two-half structure; fragments via ldmatrix.x4.
// __launch_bounds__(256, 2): cap regs at 128 so 2 blocks/SM stay resident
// (R13 measured 130 regs -> 1 block/SM -> occ 12.2%, issue 9.9%).
// ---------------------------------------------------------------------------
__device__ __forceinline__ void mma_f16(float* c,
                                        uint32_t a0, uint32_t a1, uint32_t a2, uint32_t a3,
                                        uint32_t b0, uint32_t b1) {
    asm volatile("mma.sync.aligned.m16n8k16.row.col.f32.f16.f16.f32 "
                 "{%0,%1,%2,%3}, {%4,%5,%6,%7}, {%8,%9}, {%0,%1,%2,%3};"
                 : "+f"(c[0]), "+f"(c[1]), "+f"(c[2]), "+f"(c[3])
                 : "r"(a0), "r"(a1), "r"(a2), "r"(a3), "r"(b0), "r"(b1));
}

__device__ __forceinline__ void ldsm_x4(uint32_t& r0, uint32_t& r1, uint32_t& r2, uint32_t& r3,
                                        uint32_t addr) {
    asm volatile("ldmatrix.sync.aligned.m8n8.x4.shared.b16 {%0,%1,%2,%3}, [%4];"
                 : "=r"(r0), "=r"(r1), "=r"(r2), "=r"(r3) : "r"(addr));
}

__global__ __launch_bounds__(256, 2)
void gemm_f16_kernel(const __half* __restrict__ Ah, const __half* __restrict__ Wt,
                     __half* __restrict__ C, int M) {
    __shared__ __align__(16) uint32_t sA[128][36];
    __shared__ __align__(16) uint32_t sB[128][36];

    const int tid  = threadIdx.x;
    const int wid  = tid >> 5;
    const int lane = tid & 31;
    const int g    = lane >> 2;
    const int t    = lane & 3;
    const int row0 = blockIdx.x * 128;
    const int wr   = wid * 16;

    float acc[16][4];
    #pragma unroll
    for (int i = 0; i < 16; i++)
        #pragma unroll
        for (int j = 0; j < 4; j++) acc[i][j] = 0.f;

    // per-lane ldmatrix offsets (bytes)
    const int q  = lane >> 3;        // which 8x8 matrix this lane addresses
    const int rr = lane & 7;         // row within it
    const uint32_t sA_base = (uint32_t)__cvta_generic_to_shared(&sA[0][0]);
    const uint32_t sB_base = (uint32_t)__cvta_generic_to_shared(&sB[0][0]);
    // A m16k16 fragment regs: a0=m0-7/k0-7, a1=m8-15/k0-7, a2=m0-7/k8-15, a3=m8-15/k8-15
    const uint32_t aOff = (uint32_t)(((wr + (q & 1) * 8 + rr) * 36 + (q >> 1) * 4) * 4);
    // B fragment regs: r0=n0-7/k0-7, r1=n0-7/k8-15, r2=n8-15/k0-7, r3=n8-15/k8-15
    const uint32_t bOff = (uint32_t)((((q >> 1) * 8 + rr) * 36 + (q & 1) * 4) * 4);

    for (int kh = 0; kh < 2; kh++) {
        __syncthreads();
        // stage half-K tiles: 128 rows x 32 words (64 halves); 4 uint4/thread each
        #pragma unroll
        for (int i = 0; i < 4; i++) {
            int f   = tid + i * 256;     // 0..1023
            int r   = f >> 3;            // 0..127
            int seg = f & 7;             // 0..7 (uint4 within row)
            uint4 va = make_uint4(0u, 0u, 0u, 0u);
            if (row0 + r < M)
                va = *(const uint4*)(Ah + (size_t)(row0 + r) * FDIM + kh * 64 + seg * 8);
            *(uint4*)&sA[r][seg * 4] = va;
            uint4 vb = *(const uint4*)(Wt + (size_t)r * FDIM + kh * 64 + seg * 8);
            *(uint4*)&sB[r][seg * 4] = vb;
        }
        __syncthreads();

        #pragma unroll
        for (int kt = 0; kt < 4; kt++) {
            uint32_t a0, a1, a2, a3;
            ldsm_x4(a0, a1, a2, a3, sA_base + aOff + kt * 32);
            #pragma unroll
            for (int nt2 = 0; nt2 < 8; nt2++) {
                uint32_t b00, b01, b10, b11;
                ldsm_x4(b00, b01, b10, b11,
                        sB_base + bOff + (uint32_t)(nt2 * (16 * 36 * 4)) + kt * 32);
                mma_f16(acc[2 * nt2],     a0, a1, a2, a3, b00, b01);
                mma_f16(acc[2 * nt2 + 1], a0, a1, a2, a3, b10, b11);
            }
        }
    }

    const int rA = row0 + wr + g;
    const bool g0 = rA < M;
    const bool g1 = (rA + 8) < M;
    #pragma unroll
    for (int nt = 0; nt < 16; nt++) {
        int cc = nt * 8 + 2 * t;
        if (g0) *(__half2*)(C + (size_t)rA * FDIM + cc)       = __floats2half2_rn(acc[nt][0], acc[nt][1]);
        if (g1) *(__half2*)(C + (size_t)(rA + 8) * FDIM + cc) = __floats2half2_rn(acc[nt][2], acc[nt][3]);
    }
}

// ---------------------------------------------------------------------------
// Fused CSR gather + self-loop + bias + LayerNorm + ReLU. Warp per node,
// two edges in flight (16-lane halves), uint4 feature loads, fp32 math.
// CONVERGENCE-SAFE: pair loop bound k is warp-uniform; both shuffles execute
// on all 32 lanes every iteration (clamped index); only load/acc predicated.
// ---------------------------------------------------------------------------
__global__ __launch_bounds__(256)
void aggregate_ln_relu_kernel(const __half* __restrict__ h,
                              const int* __restrict__ off, const int* __restrict__ cnt,
                              const int2* __restrict__ recs,
                              const float* __restrict__ dinv, const float* __restrict__ bias,
                              const float* __restrict__ gamma, const float* __restrict__ beta,
                              __half* __restrict__ out, int n) {
    int node = (blockIdx.x * blockDim.x + threadIdx.x) >> 5;
    int lane = threadIdx.x & 31;
    if (node >= n) return;

    const int half_id = lane >> 4;      // 0 or 1
    const int fl      = lane & 15;      // feature-chunk lane (16B each)

    float a[8];
    #pragma unroll
    for (int i = 0; i < 8; i++) a[i] = 0.f;

    int start = off[node];
    int m     = cnt[node];
    for (int base = 0; base < m; base += 32) {
        int k = min(32, m - base);
        int2 rec = make_int2(0, 0);
        if (lane < k) rec = recs[start + base + lane];
        for (int jb = 0; jb < k; jb += 2) {
            int j  = jb + half_id;
            int jj = (j < k) ? j : 0;               // clamp shuffle index
            int   sj = __shfl_sync(0xFFFFFFFFu, rec.x, jj);
            float nj = __int_as_float(__shfl_sync(0xFFFFFFFFu, rec.y, jj));
            if (j < k) {
                uint4 v = *((const uint4*)(h + (size_t)sj * FDIM) + fl);
                float2 p0 = __half22float2(*(__half2*)&v.x);
                float2 p1 = __half22float2(*(__half2*)&v.y);
                float2 p2 = __half22float2(*(__half2*)&v.z);
                float2 p3 = __half22float2(*(__half2*)&v.w);
                a[0] += p0.x * nj; a[1] += p0.y * nj;
                a[2] += p1.x * nj; a[3] += p1.y * nj;
                a[4] += p2.x * nj; a[5] += p2.y * nj;
                a[6] += p3.x * nj; a[7] += p3.y * nj;
            }
        }
    }

    // combine halves (identical feature mapping via fl)
    #pragma unroll
    for (int i = 0; i < 8; i++) a[i] += __shfl_xor_sync(0xFFFFFFFFu, a[i], 16);

    // self-loop + bias
    float di = dinv[node];
    float d2 = di * di;
    {
        uint4 v = *((const uint4*)(h + (size_t)node * FDIM) + fl);
        float2 p0 = __half22float2(*(__half2*)&v.x);
        float2 p1 = __half22float2(*(__half2*)&v.y);
        float2 p2 = __half22float2(*(__half2*)&v.z);
        float2 p3 = __half22float2(*(__half2*)&v.w);
        a[0] += p0.x * d2; a[1] += p0.y * d2;
        a[2] += p1.x * d2; a[3] += p1.y * d2;
        a[4] += p2.x * d2; a[5] += p2.y * d2;
        a[6] += p3.x * d2; a[7] += p3.y * d2;
    }
    float4 b0 = ((const float4*)bias)[2 * fl];
    float4 b1 = ((const float4*)bias)[2 * fl + 1];
    a[0] += b0.x; a[1] += b0.y; a[2] += b0.z; a[3] += b0.w;
    a[4] += b1.x; a[5] += b1.y; a[6] += b1.z; a[7] += b1.w;

    // LayerNorm (halves hold identical sums after the xor-16 combine)
    float s = a[0] + a[1] + a[2] + a[3] + a[4] + a[5] + a[6] + a[7];
    #pragma unroll
    for (int o = 8; o; o >>= 1) s += __shfl_xor_sync(0xFFFFFFFFu, s, o);
    float mu = s * (1.0f / FDIM);

    float tt[8], qv = 0.f;
    #pragma unroll
    for (int i = 0; i < 8; i++) { tt[i] = a[i] - mu; qv += tt[i] * tt[i]; }
    #pragma unroll
    for (int o = 8; o; o >>= 1) qv += __shfl_xor_sync(0xFFFFFFFFu, qv, o);
    float rstd = rsqrtf(qv * (1.0f / FDIM) + EPS);

    if (half_id == 0) {
        float4 gv0 = ((const float4*)gamma)[2 * fl];
        float4 gv1 = ((const float4*)gamma)[2 * fl + 1];
        float4 be0 = ((const float4*)beta)[2 * fl];
        float4 be1 = ((const float4*)beta)[2 * fl + 1];
        float o0 = fmaxf(tt[0] * rstd * gv0.x + be0.x, 0.f);
        float o1 = fmaxf(tt[1] * rstd * gv0.y + be0.y, 0.f);
        float o2 = fmaxf(tt[2] * rstd * gv0.z + be0.z, 0.f);
        float o3 = fmaxf(tt[3] * rstd * gv0.w + be0.w, 0.f);
        float o4 = fmaxf(tt[4] * rstd * gv1.x + be1.x, 0.f);
        float o5 = fmaxf(tt[5] * rstd * gv1.y + be1.y, 0.f);
        float o6 = fmaxf(tt[6] * rstd * gv1.z + be1.z, 0.f);
        float o7 = fmaxf(tt[7] * rstd * gv1.w + be1.w, 0.f);
        uint4 r;
        *(__half2*)&r.x = __floats2half2_rn(o0, o1);
        *(__half2*)&r.y = __floats2half2_rn(o2, o3);
        *(__half2*)&r.z = __floats2half2_rn(o4, o5);
        *(__half2*)&r.w = __floats2half2_rn(o6, o7);
        *((uint4*)(out + (size_t)node * FDIM) + fl) = r;
    }
}

// ---------------------------------------------------------------------------
// Layer 3
// ---------------------------------------------------------------------------
__global__ __launch_bounds__(256)
void gemv3_kernel(const __half* __restrict__ X, const float* __restrict__ W3,
                  float* __restrict__ h3, int n) {
    int node = (blockIdx.x * blockDim.x + threadIdx.x) >> 5;
    int lane = threadIdx.x & 31;
    if (node >= n) return;
    uint2 u = *((const uint2*)(X + (size_t)node * FDIM) + lane);
    float2 f0 = __half22float2(*(__half2*)&u.x);
    float2 f1 = __half22float2(*(__half2*)&u.y);
    float4 w = *((const float4*)W3 + lane);
    float s = f0.x * w.x + f0.y * w.y + f1.x * w.z + f1.y * w.w;
    #pragma unroll
    for (int o = 16; o; o >>= 1) s += __shfl_xor_sync(0xFFFFFFFFu, s, o);
    if (lane == 0) h3[node] = s;
}

__global__ void gather3_kernel(const float* __restrict__ h3,
                               const int* __restrict__ off, const int* __restrict__ cnt,
                               const int2* __restrict__ recs,
                               const float* __restrict__ dinv, const float* __restrict__ b3,
                               float* __restrict__ out, int n) {
    int i = blockIdx.x * blockDim.x + threadIdx.x;
    if (i >= n) return;
    float di = dinv[i];
    float acc = h3[i] * di * di;
    int start = off[i], m = cnt[i];
    for (int e = 0; e < m; e++) {
        int2 r = recs[start + e];
        acc += h3[r.x] * __int_as_float(r.y);
    }
    out[i] = acc + b3[0];
}

// ---------------------------------------------------------------------------
// Launch (gemm1 is 4th kernel -> captured by ncu window)
// ---------------------------------------------------------------------------
extern "C" void kernel_launch(void* const* d_in, const int* in_sizes, int n_in,
                              void* d_out, int out_size) {
    const float* x     = (const float*)d_in[0];
    const int*   ei    = (const int*)d_in[1];
    const float* W1    = (const float*)d_in[2];
    const float* b1    = (const float*)d_in[3];
    const float* W2    = (const float*)d_in[4];
    const float* b2    = (const float*)d_in[5];
    const float* W3    = (const float*)d_in[6];
    const float* b3    = (const float*)d_in[7];
    const float* gamma = (const float*)d_in[8];
    const float* beta  = (const float*)d_in[9];
    float*       out   = (float*)d_out;

    const int nE = in_sizes[1] / 2;
    const int n  = N_NODES;

    __half *xh, *bufA, *bufB, *w1t, *w2t;
    float  *dinv, *h3;
    int    *cnt, *off, *cursor, *part;
    int2   *recs;
    cudaGetSymbolAddress((void**)&xh,     g_xh);
    cudaGetSymbolAddress((void**)&bufA,   g_bufA);
    cudaGetSymbolAddress((void**)&bufB,   g_bufB);
    cudaGetSymbolAddress((void**)&w1t,    g_w1t);
    cudaGetSymbolAddress((void**)&w2t,    g_w2t);
    cudaGetSymbolAddress((void**)&cnt,    g_cnt);
    cudaGetSymbolAddress((void**)&off,    g_off);
    cudaGetSymbolAddress((void**)&cursor, g_cursor);
    cudaGetSymbolAddress((void**)&part,   g_part);
    cudaGetSymbolAddress((void**)&dinv,   g_dinv);
    cudaGetSymbolAddress((void**)&h3,     g_h3);
    cudaGetSymbolAddress((void**)&recs,   g_recs);

    const int egrid = (nE + 255) / 256;
    const int ngrid = (n + 255) / 256;
    const int warp_grid = (n * 32 + 255) / 256;
    const int gemm_grid = (n + 127) / 128;

    // 1-3: converts + zero
    cvt_x_kernel<<<1024, 256>>>(x, xh, n * FDIM / 4);
    cvt_w_kernel<<<(FDIM * FDIM + 255) / 256, 256>>>(W1, W2, w1t, w2t);
    zero_int_kernel<<<ngrid, 256>>>(cnt, n);

    // 4: layer-1 GEMM (profiled)
    gemm_f16_kernel<<<gemm_grid, 256>>>(xh, w1t, bufA, n);

    // 5-9: CSR build
    count_deg_kernel<<<egrid, 256>>>(ei, nE, cnt);
    partial_dinv_kernel<<<NB, 256>>>(cnt, part, dinv, n);
    scan_partials_kernel<<<1, 256>>>(part, NB);
    chunk_scan_kernel<<<NB, 256>>>(cnt, part, off, cursor, n);
    fill_kernel<<<egrid, 256>>>(ei, nE, cursor, dinv, recs);

    // 10: layer-1 aggregate
    aggregate_ln_relu_kernel<<<warp_grid, 256>>>(bufA, off, cnt, recs, dinv,
                                                 b1, gamma, beta, bufB, n);
    // 11-12: layer 2
    gemm_f16_kernel<<<gemm_grid, 256>>>(bufB, w2t, bufA, n);
    aggregate_ln_relu_kernel<<<warp_grid, 256>>>(bufA, off, cnt, recs, dinv,
                                                 b2, gamma, beta, bufB, n);
    // 13-14: layer 3
    gemv3_kernel<<<warp_grid, 256>>>(bufB, W3, h3, n);
    gather3_kernel<<<ngrid, 256>>>(h3, off, cnt, recs, dinv, b3, out, n);
}

// round 15
// speedup vs baseline: 1.6774x; 1.0216x over previous
#include <cuda_runtime.h>
#include <cuda_fp16.h>
#include <cstdint>

#define N_NODES 50000
#define N_EDGES_MAX 600000
#define FDIM    128
#define EPS     1e-5f
#define NB      ((N_NODES + 255) / 256)
#define SPAD    68   // words per smem row (full-K GEMM); 68%32=4 -> conflict-free ldsm

// ---------------------------------------------------------------------------
// Scratch (static device globals — no allocation allowed)
// ---------------------------------------------------------------------------
__device__ __align__(16) __half g_bufA[(size_t)N_NODES * FDIM];
__device__ __align__(16) __half g_bufB[(size_t)N_NODES * FDIM];
__device__ __align__(16) __half g_w1t [FDIM * FDIM];
__device__ __align__(16) __half g_w2t [FDIM * FDIM];
__device__ __align__(16) int    g_cnt   [N_NODES];
__device__ __align__(16) int    g_off   [N_NODES];
__device__ __align__(16) int    g_cursor[N_NODES];
__device__ __align__(16) int    g_part  [256];
__device__ __align__(16) float  g_dinv  [N_NODES];
__device__ __align__(16) float  g_h3    [N_NODES];
__device__ __align__(16) int2   g_recs  [N_EDGES_MAX];   // {src, nrm bits}

// ---------------------------------------------------------------------------
// Weight convert/transpose: W (fp32 [k][n]) -> Wt (fp16 [n][k])
// ---------------------------------------------------------------------------
__global__ void cvt_w_kernel(const float* __restrict__ W1, const float* __restrict__ W2,
                             __half* __restrict__ Wt1, __half* __restrict__ Wt2) {
    int idx = blockIdx.x * blockDim.x + threadIdx.x;
    if (idx >= FDIM * FDIM) return;
    int k = idx >> 7, n = idx & 127;
    Wt1[n * FDIM + k] = __float2half_rn(W1[idx]);
    Wt2[n * FDIM + k] = __float2half_rn(W2[idx]);
}

// ---------------------------------------------------------------------------
// CSR build
// ---------------------------------------------------------------------------
__global__ void zero_int_kernel(int* __restrict__ p, int n) {
    int i = blockIdx.x * blockDim.x + threadIdx.x;
    if (i < n) p[i] = 0;
}

__global__ void count_deg_kernel(const int* __restrict__ ei, int nE,
                                 int* __restrict__ cnt) {
    int e = blockIdx.x * blockDim.x + threadIdx.x;
    if (e >= nE) return;
    atomicAdd(&cnt[ei[nE + e]], 1);
}

__global__ void partial_dinv_kernel(const int* __restrict__ cnt, int* __restrict__ part,
                                    float* __restrict__ dinv, int n) {
    __shared__ int s[256];
    int t = threadIdx.x;
    int i = blockIdx.x * 256 + t;
    int c = (i < n) ? cnt[i] : 0;
    if (i < n) dinv[i] = rsqrtf((float)c + 1.0f);
    s[t] = c;
    __syncthreads();
    for (int d = 128; d > 0; d >>= 1) {
        if (t < d) s[t] += s[t + d];
        __syncthreads();
    }
    if (t == 0) part[blockIdx.x] = s[0];
}

__global__ void scan_partials_kernel(int* __restrict__ part, int nb) {
    __shared__ int s[256];
    int t = threadIdx.x;
    int v = (t < nb) ? part[t] : 0;
    s[t] = v;
    __syncthreads();
    for (int d = 1; d < 256; d <<= 1) {
        int u = (t >= d) ? s[t - d] : 0;
        __syncthreads();
        s[t] += u;
        __syncthreads();
    }
    if (t < nb) part[t] = s[t] - v;
}

__global__ void chunk_scan_kernel(const int* __restrict__ cnt, const int* __restrict__ part,
                                  int* __restrict__ off, int* __restrict__ cursor, int n) {
    __shared__ int s[256];
    int t = threadIdx.x;
    int i = blockIdx.x * 256 + t;
    int c = (i < n) ? cnt[i] : 0;
    s[t] = c;
    __syncthreads();
    for (int d = 1; d < 256; d <<= 1) {
        int u = (t >= d) ? s[t - d] : 0;
        __syncthreads();
        s[t] += u;
        __syncthreads();
    }
    if (i < n) {
        int o = part[blockIdx.x] + s[t] - c;
        off[i] = o;
        cursor[i] = o;
    }
}

__global__ void fill_kernel(const int* __restrict__ ei, int nE,
                            int* __restrict__ cursor, const float* __restrict__ dinv,
                            int2* __restrict__ recs) {
    int e = blockIdx.x * blockDim.x + threadIdx.x;
    if (e >= nE) return;
    int src = ei[e];
    int dst = ei[nE + e];
    int pos = atomicAdd(&cursor[dst], 1);
    int2 r;
    r.x = src;
    r.y = __float_as_int(dinv[src] * dinv[dst]);
    recs[pos] = r;
}

// ---------------------------------------------------------------------------
// fp16 HMMA GEMM, full-K single stage in dynamic smem (one __syncthreads).
// A input templated: fp32 (layer 1, converts during staging) or fp16.
// Tiles [128][SPAD] uint32; ldmatrix.x4 fragments; __launch_bounds__(256,2).
// ---------------------------------------------------------------------------
__device__ __forceinline__ void mma_f16(float* c,
                                        uint32_t a0, uint32_t a1, uint32_t a2, uint32_t a3,
                                        uint32_t b0, uint32_t b1) {
    asm volatile("mma.sync.aligned.m16n8k16.row.col.f32.f16.f16.f32 "
                 "{%0,%1,%2,%3}, {%4,%5,%6,%7}, {%8,%9}, {%0,%1,%2,%3};"
                 : "+f"(c[0]), "+f"(c[1]), "+f"(c[2]), "+f"(c[3])
                 : "r"(a0), "r"(a1), "r"(a2), "r"(a3), "r"(b0), "r"(b1));
}

__device__ __forceinline__ void ldsm_x4(uint32_t& r0, uint32_t& r1, uint32_t& r2, uint32_t& r3,
                                        uint32_t addr) {
    asm volatile("ldmatrix.sync.aligned.m8n8.x4.shared.b16 {%0,%1,%2,%3}, [%4];"
                 : "=r"(r0), "=r"(r1), "=r"(r2), "=r"(r3) : "r"(addr));
}

template<bool F32IN>
__global__ __launch_bounds__(256, 2)
void gemm_f16_kernel(const void* __restrict__ Ain, const __half* __restrict__ Wt,
                     __half* __restrict__ C, int M) {
    extern __shared__ __align__(16) uint32_t dyn[];
    uint32_t* sA = dyn;                 // [128][SPAD]
    uint32_t* sB = dyn + 128 * SPAD;    // [128][SPAD]

    const int tid  = threadIdx.x;
    const int wid  = tid >> 5;
    const int lane = tid & 31;
    const int g    = lane >> 2;
    const int t    = lane & 3;
    const int row0 = blockIdx.x * 128;
    const int wr   = wid * 16;

    // --- stage full tiles: 128 rows x 16 uint4 each; 8 per thread each ---
    #pragma unroll
    for (int i = 0; i < 8; i++) {
        int f = tid + i * 256;       // 0..2047
        int r = f >> 4;              // 0..127
        int q = f & 15;              // uint4 within row (8 halves)
        uint4 va = make_uint4(0u, 0u, 0u, 0u);
        if (row0 + r < M) {
            if (F32IN) {
                const float* A = (const float*)Ain;
                float4 u0 = *(const float4*)(A + (size_t)(row0 + r) * FDIM + q * 8);
                float4 u1 = *(const float4*)(A + (size_t)(row0 + r) * FDIM + q * 8 + 4);
                *(__half2*)&va.x = __floats2half2_rn(u0.x, u0.y);
                *(__half2*)&va.y = __floats2half2_rn(u0.z, u0.w);
                *(__half2*)&va.z = __floats2half2_rn(u1.x, u1.y);
                *(__half2*)&va.w = __floats2half2_rn(u1.z, u1.w);
            } else {
                const __half* A = (const __half*)Ain;
                va = *(const uint4*)(A + (size_t)(row0 + r) * FDIM + q * 8);
            }
        }
        *(uint4*)&sA[r * SPAD + q * 4] = va;
        uint4 vb = *(const uint4*)(Wt + (size_t)r * FDIM + q * 8);
        *(uint4*)&sB[r * SPAD + q * 4] = vb;
    }
    __syncthreads();

    float acc[16][4];
    #pragma unroll
    for (int i = 0; i < 16; i++)
        #pragma unroll
        for (int j = 0; j < 4; j++) acc[i][j] = 0.f;

    const int q  = lane >> 3;
    const int rr = lane & 7;
    const uint32_t sA_base = (uint32_t)__cvta_generic_to_shared(sA);
    const uint32_t sB_base = (uint32_t)__cvta_generic_to_shared(sB);
    const uint32_t aOff = (uint32_t)(((wr + (q & 1) * 8 + rr) * SPAD + (q >> 1) * 4) * 4);
    const uint32_t bOff = (uint32_t)((((q >> 1) * 8 + rr) * SPAD + (q & 1) * 4) * 4);

    #pragma unroll
    for (int kt = 0; kt < 8; kt++) {
        uint32_t a0, a1, a2, a3;
        ldsm_x4(a0, a1, a2, a3, sA_base + aOff + kt * 32);
        #pragma unroll
        for (int nt2 = 0; nt2 < 8; nt2++) {
            uint32_t b00, b01, b10, b11;
            ldsm_x4(b00, b01, b10, b11,
                    sB_base + bOff + (uint32_t)(nt2 * (16 * SPAD * 4)) + kt * 32);
            mma_f16(acc[2 * nt2],     a0, a1, a2, a3, b00, b01);
            mma_f16(acc[2 * nt2 + 1], a0, a1, a2, a3, b10, b11);
        }
    }

    const int rA = row0 + wr + g;
    const bool g0 = rA < M;
    const bool g1 = (rA + 8) < M;
    #pragma unroll
    for (int nt = 0; nt < 16; nt++) {
        int cc = nt * 8 + 2 * t;
        if (g0) *(__half2*)(C + (size_t)rA * FDIM + cc)       = __floats2half2_rn(acc[nt][0], acc[nt][1]);
        if (g1) *(__half2*)(C + (size_t)(rA + 8) * FDIM + cc) = __floats2half2_rn(acc[nt][2], acc[nt][3]);
    }
}

// ---------------------------------------------------------------------------
// Fused CSR gather + self-loop + bias + LayerNorm + ReLU (+ optional W3 dot).
// Warp per node, two edges in flight (16-lane halves), uint4 loads, fp32 math.
// Convergence-safe pair loop (k warp-uniform; shuffles unconditional).
// ---------------------------------------------------------------------------
template<bool FUSE_W3>
__global__ __launch_bounds__(256)
void aggregate_ln_relu_kernel(const __half* __restrict__ h,
                              const int* __restrict__ off, const int* __restrict__ cnt,
                              const int2* __restrict__ recs,
                              const float* __restrict__ dinv, const float* __restrict__ bias,
                              const float* __restrict__ gamma, const float* __restrict__ beta,
                              __half* __restrict__ out,
                              const float* __restrict__ W3, float* __restrict__ h3, int n) {
    int node = (blockIdx.x * blockDim.x + threadIdx.x) >> 5;
    int lane = threadIdx.x & 31;
    if (node >= n) return;

    const int half_id = lane >> 4;
    const int fl      = lane & 15;

    float a[8];
    #pragma unroll
    for (int i = 0; i < 8; i++) a[i] = 0.f;

    int start = off[node];
    int m     = cnt[node];
    for (int base = 0; base < m; base += 32) {
        int k = min(32, m - base);
        int2 rec = make_int2(0, 0);
        if (lane < k) rec = recs[start + base + lane];
        for (int jb = 0; jb < k; jb += 2) {
            int j  = jb + half_id;
            int jj = (j < k) ? j : 0;
            int   sj = __shfl_sync(0xFFFFFFFFu, rec.x, jj);
            float nj = __int_as_float(__shfl_sync(0xFFFFFFFFu, rec.y, jj));
            if (j < k) {
                uint4 v = *((const uint4*)(h + (size_t)sj * FDIM) + fl);
                float2 p0 = __half22float2(*(__half2*)&v.x);
                float2 p1 = __half22float2(*(__half2*)&v.y);
                float2 p2 = __half22float2(*(__half2*)&v.z);
                float2 p3 = __half22float2(*(__half2*)&v.w);
                a[0] += p0.x * nj; a[1] += p0.y * nj;
                a[2] += p1.x * nj; a[3] += p1.y * nj;
                a[4] += p2.x * nj; a[5] += p2.y * nj;
                a[6] += p3.x * nj; a[7] += p3.y * nj;
            }
        }
    }

    #pragma unroll
    for (int i = 0; i < 8; i++) a[i] += __shfl_xor_sync(0xFFFFFFFFu, a[i], 16);

    float di = dinv[node];
    float d2 = di * di;
    {
        uint4 v = *((const uint4*)(h + (size_t)node * FDIM) + fl);
        float2 p0 = __half22float2(*(__half2*)&v.x);
        float2 p1 = __half22float2(*(__half2*)&v.y);
        float2 p2 = __half22float2(*(__half2*)&v.z);
        float2 p3 = __half22float2(*(__half2*)&v.w);
        a[0] += p0.x * d2; a[1] += p0.y * d2;
        a[2] += p1.x * d2; a[3] += p1.y * d2;
        a[4] += p2.x * d2; a[5] += p2.y * d2;
        a[6] += p3.x * d2; a[7] += p3.y * d2;
    }
    float4 b0 = ((const float4*)bias)[2 * fl];
    float4 b1 = ((const float4*)bias)[2 * fl + 1];
    a[0] += b0.x; a[1] += b0.y; a[2] += b0.z; a[3] += b0.w;
    a[4] += b1.x; a[5] += b1.y; a[6] += b1.z; a[7] += b1.w;

    float s = a[0] + a[1] + a[2] + a[3] + a[4] + a[5] + a[6] + a[7];
    #pragma unroll
    for (int o = 8; o; o >>= 1) s += __shfl_xor_sync(0xFFFFFFFFu, s, o);
    float mu = s * (1.0f / FDIM);

    float tt[8], qv = 0.f;
    #pragma unroll
    for (int i = 0; i < 8; i++) { tt[i] = a[i] - mu; qv += tt[i] * tt[i]; }
    #pragma unroll
    for (int o = 8; o; o >>= 1) qv += __shfl_xor_sync(0xFFFFFFFFu, qv, o);
    float rstd = rsqrtf(qv * (1.0f / FDIM) + EPS);

    float4 gv0 = ((const float4*)gamma)[2 * fl];
    float4 gv1 = ((const float4*)gamma)[2 * fl + 1];
    float4 be0 = ((const float4*)beta)[2 * fl];
    float4 be1 = ((const float4*)beta)[2 * fl + 1];
    float o0 = fmaxf(tt[0] * rstd * gv0.x + be0.x, 0.f);
    float o1 = fmaxf(tt[1] * rstd * gv0.y + be0.y, 0.f);
    float o2 = fmaxf(tt[2] * rstd * gv0.z + be0.z, 0.f);
    float o3 = fmaxf(tt[3] * rstd * gv0.w + be0.w, 0.f);
    float o4 = fmaxf(tt[4] * rstd * gv1.x + be1.x, 0.f);
    float o5 = fmaxf(tt[5] * rstd * gv1.y + be1.y, 0.f);
    float o6 = fmaxf(tt[6] * rstd * gv1.z + be1.z, 0.f);
    float o7 = fmaxf(tt[7] * rstd * gv1.w + be1.w, 0.f);

    if (half_id == 0) {
        uint4 r;
        *(__half2*)&r.x = __floats2half2_rn(o0, o1);
        *(__half2*)&r.y = __floats2half2_rn(o2, o3);
        *(__half2*)&r.z = __floats2half2_rn(o4, o5);
        *(__half2*)&r.w = __floats2half2_rn(o6, o7);
        *((uint4*)(out + (size_t)node * FDIM) + fl) = r;
    }

    if (FUSE_W3) {
        // dot(relu_out, W3): each half holds the full row (fl-mapped); use lanes 0-15.
        float4 w0 = ((const float4*)W3)[2 * fl];
        float4 w1 = ((const float4*)W3)[2 * fl + 1];
        float s3 = o0 * w0.x + o1 * w0.y + o2 * w0.z + o3 * w0.w
                 + o4 * w1.x + o5 * w1.y + o6 * w1.z + o7 * w1.w;
        #pragma unroll
        for (int o = 8; o; o >>= 1) s3 += __shfl_xor_sync(0xFFFFFFFFu, s3, o);
        if (lane == 0) h3[node] = s3;
    }
}

// ---------------------------------------------------------------------------
// Layer-3 gather (thread per node)
// ---------------------------------------------------------------------------
__global__ void gather3_kernel(const float* __restrict__ h3,
                               const int* __restrict__ off, const int* __restrict__ cnt,
                               const int2* __restrict__ recs,
                               const float* __restrict__ dinv, const float* __restrict__ b3,
                               float* __restrict__ out, int n) {
    int i = blockIdx.x * blockDim.x + threadIdx.x;
    if (i >= n) return;
    float di = dinv[i];
    float acc = h3[i] * di * di;
    int start = off[i], m = cnt[i];
    for (int e = 0; e < m; e++) {
        int2 r = recs[start + e];
        acc += h3[r.x] * __int_as_float(r.y);
    }
    out[i] = acc + b3[0];
}

// ---------------------------------------------------------------------------
// Launch (gemm1 is 4th user kernel -> captured by ncu window)
// ---------------------------------------------------------------------------
extern "C" void kernel_launch(void* const* d_in, const int* in_sizes, int n_in,
                              void* d_out, int out_size) {
    const float* x     = (const float*)d_in[0];
    const int*   ei    = (const int*)d_in[1];
    const float* W1    = (const float*)d_in[2];
    const float* b1    = (const float*)d_in[3];
    const float* W2    = (const float*)d_in[4];
    const float* b2    = (const float*)d_in[5];
    const float* W3    = (const float*)d_in[6];
    const float* b3    = (const float*)d_in[7];
    const float* gamma = (const float*)d_in[8];
    const float* beta  = (const float*)d_in[9];
    float*       out   = (float*)d_out;

    const int nE = in_sizes[1] / 2;
    const int n  = N_NODES;

    __half *bufA, *bufB, *w1t, *w2t;
    float  *dinv, *h3;
    int    *cnt, *off, *cursor, *part;
    int2   *recs;
    cudaGetSymbolAddress((void**)&bufA,   g_bufA);
    cudaGetSymbolAddress((void**)&bufB,   g_bufB);
    cudaGetSymbolAddress((void**)&w1t,    g_w1t);
    cudaGetSymbolAddress((void**)&w2t,    g_w2t);
    cudaGetSymbolAddress((void**)&cnt,    g_cnt);
    cudaGetSymbolAddress((void**)&off,    g_off);
    cudaGetSymbolAddress((void**)&cursor, g_cursor);
    cudaGetSymbolAddress((void**)&part,   g_part);
    cudaGetSymbolAddress((void**)&dinv,   g_dinv);
    cudaGetSymbolAddress((void**)&h3,     g_h3);
    cudaGetSymbolAddress((void**)&recs,   g_recs);

    const int egrid = (nE + 255) / 256;
    const int ngrid = (n + 255) / 256;
    const int warp_grid = (n * 32 + 255) / 256;
    const int gemm_grid = (n + 127) / 128;
    const int gemm_smem = 2 * 128 * SPAD * 4;   // 69632 B

    cudaFuncSetAttribute(gemm_f16_kernel<true>,
                         cudaFuncAttributeMaxDynamicSharedMemorySize, gemm_smem);
    cudaFuncSetAttribute(gemm_f16_kernel<false>,
                         cudaFuncAttributeMaxDynamicSharedMemorySize, gemm_smem);

    // 1-3
    zero_int_kernel<<<ngrid, 256>>>(cnt, n);
    cvt_w_kernel<<<(FDIM * FDIM + 255) / 256, 256>>>(W1, W2, w1t, w2t);
    count_deg_kernel<<<egrid, 256>>>(ei, nE, cnt);

    // 4: layer-1 GEMM, fp32 input (profiled)
    gemm_f16_kernel<true><<<gemm_grid, 256, gemm_smem>>>(x, w1t, bufA, n);

    // 5-8: rest of CSR build
    partial_dinv_kernel<<<NB, 256>>>(cnt, part, dinv, n);
    scan_partials_kernel<<<1, 256>>>(part, NB);
    chunk_scan_kernel<<<NB, 256>>>(cnt, part, off, cursor, n);
    fill_kernel<<<egrid, 256>>>(ei, nE, cursor, dinv, recs);

    // 9: layer-1 aggregate
    aggregate_ln_relu_kernel<false><<<warp_grid, 256>>>(bufA, off, cnt, recs, dinv,
                                                        b1, gamma, beta, bufB,
                                                        nullptr, nullptr, n);
    // 10-11: layer 2 (aggregate fuses the W3 GEMV -> h3)
    gemm_f16_kernel<false><<<gemm_grid, 256, gemm_smem>>>(bufB, w2t, bufA, n);
    aggregate_ln_relu_kernel<true><<<warp_grid, 256>>>(bufA, off, cnt, recs, dinv,
                                                       b2, gamma, beta, bufB,
                                                       W3, h3, n);
    // 12: layer-3 gather
    gather3_kernel<<<ngrid, 256>>>(h3, off, cnt, recs, dinv, b3, out, n);
}